// round 10
// baseline (speedup 1.0000x reference)
#include <cuda_runtime.h>
#include <math.h>
#include <stdint.h>

// ---------------------------------------------------------------------------
// MGDT forward. tf32 tensor-core linears with producer-side tf32 rounding +
// 32-column mma-layout permutation (vectorized cvt-free fragment loads),
// cp.async double-buffered mainloop; fused fp32 flash attention; fp32 patch
// embed. Shapes: B=8 T=16 C=4 H=W=84 P=14 NT=36 TPS=39 L=624 D=512 NH=8
// DH=64 NL=6 DFF=2048.
// ---------------------------------------------------------------------------

namespace cfg {
constexpr int B = 8, T = 16, C = 4, H = 84, W = 84, P = 14;
constexpr int NT = 36, TPS = 39, L = 624;
constexpr int D = 512, NH = 8, DH = 64, NL = 6, DFF = 2048;
constexpr int NRET = 120, NACT = 18, NREW = 3;
constexpr int ROWS = B * L;            // 4992
constexpr int NPATCH = B * T * NT;     // 4608
constexpr int PDIM = C * P * P;        // 784
}

using namespace cfg;

// permuted tf32 weight scratch offsets
constexpr long WTF_QKV = 0;
constexpr long WTF_OUT = (long)NL * 3 * D * D;          // 4718592
constexpr long WTF_F1  = WTF_OUT + (long)NL * D * D;    // 6291456
constexpr long WTF_F2  = WTF_F1 + (long)NL * DFF * D;   // 12582912
constexpr long WTF_TOTAL = WTF_F2 + (long)NL * D * DFF; // 18874368

// -------------------- scratch (device globals; no runtime alloc) -----------
__device__ float g_patches[NPATCH * PDIM];
__device__ float g_x[ROWS * D];
__device__ float g_xn[ROWS * D];          // PERMUTED+tf32 (GEMM-A only)
__device__ float g_qkv[ROWS * 3 * D];     // normal (flash input)
__device__ float g_o[ROWS * D];           // patch path: normal; attn out: PERM+tf32
__device__ float g_hid[ROWS * DFF];       // PERMUTED+tf32 (GEMM-A only)
__device__ float g_wtf[WTF_TOTAL];        // PERMUTED+tf32 weights

__device__ __forceinline__ float ftf32(float x) {
    uint32_t u;
    asm("cvt.rna.tf32.f32 %0, %1;" : "=r"(u) : "f"(x));
    return __uint_as_float(u);
}

// within-32 mma fragment permutation: k -> (k&3)*8 + k/4
__device__ __forceinline__ int perm32(int k) { return ((k & 3) << 3) | (k >> 2); }
__device__ __forceinline__ int pcol(int c) { return (c & ~31) | perm32(c & 31); }

// -------------------- weight prep: round to tf32 + permute ------------------
__global__ void wprep_kernel(const float* __restrict__ src, float* __restrict__ dst,
                             int total) {
    int i = blockIdx.x * blockDim.x + threadIdx.x;
    if (i >= total) return;
    dst[(i & ~31) | perm32(i & 31)] = ftf32(src[i]);
}

// -------------------- patch extraction -------------------------------------
__global__ void patchify_kernel(const float* __restrict__ frames) {
    int i = blockIdx.x * blockDim.x + threadIdx.x;
    if (i >= NPATCH * PDIM) return;
    int prow = i / PDIM, f = i - prow * PDIM;
    int bt = prow / NT, n = prow - bt * NT;
    int gy = n / 6, gx = n - gy * 6;
    int c = f / (P * P);
    int r = f - c * P * P;
    int py = r / P, px = r - py * P;
    long src = (((long)bt * C + c) * H + gy * P + py) * W + gx * P + px;
    g_patches[i] = frames[src];
}

// -------------------- fp32 GEMM (patch embed only) --------------------------
template <int EPI>
__global__ void gemm_kernel(const float* __restrict__ A, const float* __restrict__ Wm,
                            const float* __restrict__ bias, const float* __restrict__ res,
                            float* __restrict__ Cmat, int M, int N, int K) {
    __shared__ float As[16][68];
    __shared__ float Bs[16][68];
    int tid = threadIdx.x;
    int bm = blockIdx.y * 64, bn = blockIdx.x * 64;
    int lr = tid >> 2;
    int lk = (tid & 3) * 4;
    int ty = tid >> 4, tx = tid & 15;
    float acc[4][4] = {};
    const float* Aptr = A + (long)(bm + lr) * K + lk;
    const float* Wptr = Wm + (long)(bn + lr) * K + lk;
    for (int k0 = 0; k0 < K; k0 += 16) {
        float4 av = *(const float4*)(Aptr + k0);
        float4 wv = *(const float4*)(Wptr + k0);
        As[lk + 0][lr] = av.x; As[lk + 1][lr] = av.y;
        As[lk + 2][lr] = av.z; As[lk + 3][lr] = av.w;
        Bs[lk + 0][lr] = wv.x; Bs[lk + 1][lr] = wv.y;
        Bs[lk + 2][lr] = wv.z; Bs[lk + 3][lr] = wv.w;
        __syncthreads();
#pragma unroll
        for (int kk = 0; kk < 16; kk++) {
            float4 a4 = *(const float4*)&As[kk][ty * 4];
            float4 b4 = *(const float4*)&Bs[kk][tx * 4];
            float ar[4] = {a4.x, a4.y, a4.z, a4.w};
            float br[4] = {b4.x, b4.y, b4.z, b4.w};
#pragma unroll
            for (int i = 0; i < 4; i++)
#pragma unroll
                for (int j = 0; j < 4; j++)
                    acc[i][j] = fmaf(ar[i], br[j], acc[i][j]);
        }
        __syncthreads();
    }
#pragma unroll
    for (int i = 0; i < 4; i++) {
        int row = bm + ty * 4 + i;
#pragma unroll
        for (int j = 0; j < 4; j++) {
            int col = bn + tx * 4 + j;
            float v = acc[i][j] + bias[col];
            if (EPI == 1) v += res[(long)row * N + col];
            if (EPI == 2) v = 0.5f * v * (1.0f + erff(v * 0.70710678118654752f));
            Cmat[(long)row * N + col] = v;
        }
    }
}

// -------------------- tf32 MMA GEMM, permuted inputs ------------------------
// C = A(MxK) @ W(NxK)^T + bias. A and W in gmem are tf32-rounded fp32 with
// 32-col fragment permutation (perm32). Block 128x64, 8 warps, warp 32x32,
// k-tile 32, 2-stage cp.async. Fragment loads: 16x LDS.128/thread/k-tile.
// EPI: 0 none, 1 residual add, 2 exact GELU.  CPERM: permute C columns
// (for outputs that feed a later GEMM as A).
constexpr int MG_STAGE_FLOATS = 128 * 36 + 64 * 36;      // 6912
constexpr int MG_SMEM_BYTES = 2 * MG_STAGE_FLOATS * 4;   // 55296

template <int EPI, int CPERM>
__global__ __launch_bounds__(256) void mma_gemm_kernel(
        const float* __restrict__ A, const float* __restrict__ Wm,
        const float* __restrict__ bias, const float* __restrict__ res,
        float* __restrict__ Cmat, int M, int N, int K) {
    extern __shared__ float mg_smem[];
    int tid = threadIdx.x;
    int bm = blockIdx.y * 128, bn = blockIdx.x * 64;
    int warp = tid >> 5, lane = tid & 31;
    int grp = lane >> 2, qd = lane & 3;
    int wm0 = (warp >> 1) * 32, wn0 = (warp & 1) * 32;
    float acc[2][4][4] = {};

    int arow = tid >> 3;             // 0..31
    int af4 = (tid & 7) * 4;         // 0..28

    auto prefetch = [&](int k0, int s) {
        float* As = mg_smem + s * MG_STAGE_FLOATS;
        float* Bs = As + 128 * 36;
#pragma unroll
        for (int i = 0; i < 4; i++) {
            int r = arow + 32 * i;
            uint32_t dst = (uint32_t)__cvta_generic_to_shared(&As[r * 36 + af4]);
            const float* src = A + (long)(bm + r) * K + k0 + af4;
            asm volatile("cp.async.cg.shared.global [%0], [%1], 16;\n"
                         :: "r"(dst), "l"(src));
        }
#pragma unroll
        for (int i = 0; i < 2; i++) {
            int idx = tid + 256 * i;
            int r = idx >> 3;
            int f4 = (idx & 7) * 4;
            uint32_t dst = (uint32_t)__cvta_generic_to_shared(&Bs[r * 36 + f4]);
            const float* src = Wm + (long)(bn + r) * K + k0 + f4;
            asm volatile("cp.async.cg.shared.global [%0], [%1], 16;\n"
                         :: "r"(dst), "l"(src));
        }
        asm volatile("cp.async.commit_group;\n");
    };

    int KT = K / 32;
    prefetch(0, 0);
    for (int kt = 0; kt < KT; kt++) {
        if (kt + 1 < KT) {
            prefetch((kt + 1) * 32, (kt + 1) & 1);
            asm volatile("cp.async.wait_group 1;\n");
        } else {
            asm volatile("cp.async.wait_group 0;\n");
        }
        __syncthreads();
        const float* As = mg_smem + (kt & 1) * MG_STAGE_FLOATS;
        const float* Bs = As + 128 * 36;

        // vectorized fragment loads (permuted layout -> contiguous 8 floats)
        float af[4][8];
        float bf[4][8];
#pragma unroll
        for (int rr = 0; rr < 4; rr++) {
            int r = wm0 + rr * 8 + grp;
            *(float4*)&af[rr][0] = *(const float4*)&As[r * 36 + qd * 8];
            *(float4*)&af[rr][4] = *(const float4*)&As[r * 36 + qd * 8 + 4];
        }
#pragma unroll
        for (int nn = 0; nn < 4; nn++) {
            int c = wn0 + nn * 8 + grp;
            *(float4*)&bf[nn][0] = *(const float4*)&Bs[c * 36 + qd * 8];
            *(float4*)&bf[nn][4] = *(const float4*)&Bs[c * 36 + qd * 8 + 4];
        }

#pragma unroll
        for (int ks = 0; ks < 4; ks++) {
#pragma unroll
            for (int mi = 0; mi < 2; mi++)
#pragma unroll
                for (int ni = 0; ni < 4; ni++)
                    asm volatile(
                        "mma.sync.aligned.m16n8k8.row.col.f32.tf32.tf32.f32 "
                        "{%0,%1,%2,%3},{%4,%5,%6,%7},{%8,%9},{%0,%1,%2,%3};\n"
                        : "+f"(acc[mi][ni][0]), "+f"(acc[mi][ni][1]),
                          "+f"(acc[mi][ni][2]), "+f"(acc[mi][ni][3])
                        : "r"(__float_as_uint(af[2 * mi][2 * ks])),
                          "r"(__float_as_uint(af[2 * mi + 1][2 * ks])),
                          "r"(__float_as_uint(af[2 * mi][2 * ks + 1])),
                          "r"(__float_as_uint(af[2 * mi + 1][2 * ks + 1])),
                          "r"(__float_as_uint(bf[ni][2 * ks])),
                          "r"(__float_as_uint(bf[ni][2 * ks + 1])));
        }
        __syncthreads();
    }
#pragma unroll
    for (int mi = 0; mi < 2; mi++) {
#pragma unroll
        for (int ni = 0; ni < 4; ni++) {
            int r = bm + wm0 + mi * 16 + grp;
            int c = bn + wn0 + ni * 8 + 2 * qd;
            float b0 = bias[c], b1 = bias[c + 1];
#pragma unroll
            for (int h = 0; h < 2; h++) {
                int row = r + 8 * h;
                float v0 = acc[mi][ni][2 * h + 0] + b0;
                float v1 = acc[mi][ni][2 * h + 1] + b1;
                if (EPI == 1) {
                    const float2 rr = *(const float2*)(res + (long)row * N + c);
                    v0 += rr.x; v1 += rr.y;
                }
                if (EPI == 2) {
                    v0 = 0.5f * v0 * (1.0f + erff(v0 * 0.70710678118654752f));
                    v1 = 0.5f * v1 * (1.0f + erff(v1 * 0.70710678118654752f));
                }
                if (CPERM) {
                    Cmat[(long)row * N + pcol(c)]     = ftf32(v0);
                    Cmat[(long)row * N + pcol(c + 1)] = ftf32(v1);
                } else {
                    *(float2*)(Cmat + (long)row * N + c) = make_float2(v0, v1);
                }
            }
        }
    }
}

// -------------------- layernorm (writes PERMUTED tf32 for GEMM-A) ----------
__global__ void ln_kernel(const float* __restrict__ s, const float* __restrict__ bta,
                          const float* __restrict__ in, float* __restrict__ out) {
    int row = blockIdx.x;
    const float* x = in + (long)row * D;
    int tid = threadIdx.x;
    float v0 = x[tid], v1 = x[tid + 256];
    __shared__ float red[256];
    red[tid] = v0 + v1;
    __syncthreads();
    for (int st = 128; st > 0; st >>= 1) {
        if (tid < st) red[tid] += red[tid + st];
        __syncthreads();
    }
    float mu = red[0] * (1.0f / 512.0f);
    __syncthreads();
    float d0 = v0 - mu, d1 = v1 - mu;
    red[tid] = d0 * d0 + d1 * d1;
    __syncthreads();
    for (int st = 128; st > 0; st >>= 1) {
        if (tid < st) red[tid] += red[tid + st];
        __syncthreads();
    }
    float rstd = rsqrtf(red[0] * (1.0f / 512.0f) + 1e-5f);
    float* o = out + (long)row * D;
    o[pcol(tid)]       = ftf32(d0 * rstd * s[tid]       + bta[tid]);
    o[pcol(tid + 256)] = ftf32(d1 * rstd * s[tid + 256] + bta[tid + 256]);
}

// -------------------- token assembly ----------------------------------------
__global__ void assemble_kernel(const int* __restrict__ rtg, const int* __restrict__ act,
                                const int* __restrict__ rew, const int* __restrict__ gid,
                                const float* __restrict__ ret_e, const float* __restrict__ act_e,
                                const float* __restrict__ rew_e, const float* __restrict__ game_e,
                                const float* __restrict__ pos_e, const float* __restrict__ type_e) {
    int row = blockIdx.x;
    int b = row / L, l = row - b * L;
    int t = l / TPS, off = l - t * TPS;
    int tid = threadIdx.x;
    const float* src;
    int typ;
    if (off < NT)           { src = g_o + ((long)(b * T + t) * NT + off) * D; typ = 0; }
    else if (off == NT)     { src = ret_e + (long)rtg[b * T + t] * D;        typ = 1; }
    else if (off == NT + 1) { src = act_e + (long)act[b * T + t] * D;        typ = 2; }
    else                    { src = rew_e + (long)rew[b * T + t] * D;        typ = 3; }
    int g = gid[b];
    float* dst = g_x + (long)row * D;
    for (int d = tid; d < D; d += blockDim.x)
        dst[d] = src[d] + pos_e[(long)l * D + d] + type_e[(long)typ * D + d]
               + game_e[(long)g * D + d];
}

// -------------------- fused flash attention (fp32, dynamic smem) ------------
// Mask is a per-row PREFIX: allowed(q,k) <=> k <= klim(q); klim monotone in q.
// Epilogue writes g_o PERMUTED+tf32 (consumed only by out-proj GEMM as A).
constexpr int FA_TILE_FLOATS = 64 * 68;
constexpr int FA_SMEM_BYTES = 4 * FA_TILE_FLOATS * 4;

__global__ __launch_bounds__(256) void flash_attn_kernel() {
    extern __shared__ float fa_smem[];
    float (*Qs)[68] = (float(*)[68])(fa_smem);                      // [d][q]
    float (*Ks)[68] = (float(*)[68])(fa_smem + FA_TILE_FLOATS);     // [d][k]
    float (*Vs)[68] = (float(*)[68])(fa_smem + 2 * FA_TILE_FLOATS); // [k][d]
    float (*Ps)[68] = (float(*)[68])(fa_smem + 3 * FA_TILE_FLOATS); // [k][q]
    int bh = blockIdx.y;
    int b = bh >> 3, h = bh & 7;
    int q0 = blockIdx.x * 64;
    int tid = threadIdx.x;
    int ty = tid >> 4, tx = tid & 15;
    const float* qbase = g_qkv + (long)b * L * (3 * D) + h * DH;
    const float* kbase = qbase + D;
    const float* vbase = qbase + 2 * D;

#pragma unroll
    for (int r = 0; r < 4; r++) {
        int c = r * 256 + tid;
        int row = c >> 4;
        int d4 = (c & 15) * 4;
        float4 qv = make_float4(0, 0, 0, 0);
        int gq = q0 + row;
        if (gq < L) qv = *(const float4*)(qbase + (long)gq * (3 * D) + d4);
        Qs[d4 + 0][row] = qv.x; Qs[d4 + 1][row] = qv.y;
        Qs[d4 + 2][row] = qv.z; Qs[d4 + 3][row] = qv.w;
    }

    float m[4], l[4], acc[4][4];
#pragma unroll
    for (int i = 0; i < 4; i++) {
        m[i] = -1e30f; l[i] = 0.0f;
#pragma unroll
        for (int j = 0; j < 4; j++) acc[i][j] = 0.0f;
    }

    int klim[4];
#pragma unroll
    for (int i = 0; i < 4; i++) {
        int q = q0 + ty * 4 + i;
        if (q >= L) klim[i] = 0;
        else {
            int st = q / TPS, off = q - st * TPS;
            klim[i] = (off < NT) ? st * TPS + NT - 1 : q;
        }
    }
    int qlast = min(q0 + 63, L - 1);
    int stl = qlast / TPS, offl = qlast - stl * TPS;
    int klim_max = (offl < NT) ? stl * TPS + NT - 1 : qlast;
    int nkt = klim_max / 64 + 1;

    for (int kt = 0; kt < nkt; kt++) {
        int k0 = kt * 64;
#pragma unroll
        for (int r = 0; r < 4; r++) {
            int c = r * 256 + tid;
            int row = c >> 4;
            int d4 = (c & 15) * 4;
            int gk = k0 + row;
            float4 kv = make_float4(0, 0, 0, 0), vv = make_float4(0, 0, 0, 0);
            if (gk < L) {
                kv = *(const float4*)(kbase + (long)gk * (3 * D) + d4);
                vv = *(const float4*)(vbase + (long)gk * (3 * D) + d4);
            }
            Ks[d4 + 0][row] = kv.x; Ks[d4 + 1][row] = kv.y;
            Ks[d4 + 2][row] = kv.z; Ks[d4 + 3][row] = kv.w;
            *(float4*)&Vs[row][d4] = vv;
        }
        __syncthreads();

        float s[4][4] = {};
#pragma unroll 8
        for (int d = 0; d < 64; d++) {
            float4 a4 = *(const float4*)&Qs[d][ty * 4];
            float4 b4 = *(const float4*)&Ks[d][tx * 4];
            float ar[4] = {a4.x, a4.y, a4.z, a4.w};
            float br[4] = {b4.x, b4.y, b4.z, b4.w};
#pragma unroll
            for (int i = 0; i < 4; i++)
#pragma unroll
                for (int j = 0; j < 4; j++)
                    s[i][j] = fmaf(ar[i], br[j], s[i][j]);
        }

#pragma unroll
        for (int i = 0; i < 4; i++) {
            float rm = -1e30f;
#pragma unroll
            for (int j = 0; j < 4; j++) {
                int k = k0 + tx * 4 + j;
                s[i][j] = (k <= klim[i]) ? s[i][j] * 0.125f : -1e30f;
                rm = fmaxf(rm, s[i][j]);
            }
#pragma unroll
            for (int w = 1; w < 16; w <<= 1)
                rm = fmaxf(rm, __shfl_xor_sync(0xffffffffu, rm, w));
            float mn = fmaxf(m[i], rm);
            float corr = __expf(m[i] - mn);
            float rs = 0.0f;
#pragma unroll
            for (int j = 0; j < 4; j++) {
                float p = __expf(s[i][j] - mn);
                s[i][j] = p;
                rs += p;
            }
#pragma unroll
            for (int w = 1; w < 16; w <<= 1)
                rs += __shfl_xor_sync(0xffffffffu, rs, w);
            l[i] = l[i] * corr + rs;
            m[i] = mn;
#pragma unroll
            for (int j = 0; j < 4; j++) acc[i][j] *= corr;
        }

        __syncthreads();
#pragma unroll
        for (int j = 0; j < 4; j++) {
            float4 pv = make_float4(s[0][j], s[1][j], s[2][j], s[3][j]);
            *(float4*)&Ps[tx * 4 + j][ty * 4] = pv;
        }
        __syncthreads();

#pragma unroll 8
        for (int k = 0; k < 64; k++) {
            float4 a4 = *(const float4*)&Ps[k][ty * 4];
            float4 b4 = *(const float4*)&Vs[k][tx * 4];
            float ar[4] = {a4.x, a4.y, a4.z, a4.w};
            float br[4] = {b4.x, b4.y, b4.z, b4.w};
#pragma unroll
            for (int i = 0; i < 4; i++)
#pragma unroll
                for (int j = 0; j < 4; j++)
                    acc[i][j] = fmaf(ar[i], br[j], acc[i][j]);
        }
        __syncthreads();
    }

    // epilogue: O = acc / l, tf32-rounded + column-permuted for out-proj GEMM
    float* obase = g_o + (long)b * L * D;
#pragma unroll
    for (int i = 0; i < 4; i++) {
        int q = q0 + ty * 4 + i;
        if (q >= L) continue;
        float inv = 1.0f / l[i];
#pragma unroll
        for (int j = 0; j < 4; j++) {
            int c = h * DH + tx * 4 + j;
            obase[(long)q * D + pcol(c)] = ftf32(acc[i][j] * inv);
        }
    }
}

// -------------------- heads -------------------------------------------------
__global__ void heads_kernel(const float* __restrict__ rw, const float* __restrict__ rb,
                             const float* __restrict__ aw, const float* __restrict__ ab,
                             const float* __restrict__ ww, const float* __restrict__ wb,
                             float* __restrict__ out) {
    int bt = blockIdx.x;
    int b = bt / T, t = bt - b * T;
    __shared__ float hsh[3][D];
    int tid = threadIdx.x;
    const float* base = g_x + ((long)b * L + (long)t * TPS + (NT - 1)) * D;
    for (int d = tid; d < 3 * D; d += blockDim.x)
        hsh[d / D][d % D] = base[d];
    __syncthreads();
    if (tid < NRET) {
        float s = rb[tid];
        for (int k = 0; k < D; k++) s = fmaf(hsh[0][k], rw[(long)tid * D + k], s);
        out[(long)bt * NRET + tid] = s;
    } else if (tid < NRET + NACT) {
        int j = tid - NRET;
        float s = ab[j];
        for (int k = 0; k < D; k++) s = fmaf(hsh[1][k], aw[(long)j * D + k], s);
        out[(long)B * T * NRET + (long)bt * NACT + j] = s;
    } else if (tid < NRET + NACT + NREW) {
        int j = tid - NRET - NACT;
        float s = wb[j];
        for (int k = 0; k < D; k++) s = fmaf(hsh[2][k], ww[(long)j * D + k], s);
        out[(long)B * T * (NRET + NACT) + (long)bt * NREW + j] = s;
    }
}

// -------------------- launch ------------------------------------------------
extern "C" void kernel_launch(void* const* d_in, const int* in_sizes, int n_in,
                              void* d_out, int out_size) {
    const float* frames   = (const float*)d_in[0];
    const int*   rtg      = (const int*)d_in[1];
    const int*   actions  = (const int*)d_in[2];
    const int*   rewards  = (const int*)d_in[3];
    const int*   gids     = (const int*)d_in[4];
    const float* patch_w  = (const float*)d_in[5];
    const float* patch_b  = (const float*)d_in[6];
    const float* ret_e    = (const float*)d_in[7];
    const float* act_e    = (const float*)d_in[8];
    const float* rew_e    = (const float*)d_in[9];
    const float* game_e   = (const float*)d_in[10];
    const float* pos_e    = (const float*)d_in[11];
    const float* type_e   = (const float*)d_in[12];
    const float* qkv_w    = (const float*)d_in[13];
    const float* qkv_b    = (const float*)d_in[14];
    const float* out_w    = (const float*)d_in[15];
    const float* out_b    = (const float*)d_in[16];
    const float* ln1_s    = (const float*)d_in[17];
    const float* ln1_b    = (const float*)d_in[18];
    const float* ln2_s    = (const float*)d_in[19];
    const float* ln2_b    = (const float*)d_in[20];
    const float* ffn_w1   = (const float*)d_in[21];
    const float* ffn_b1   = (const float*)d_in[22];
    const float* ffn_w2   = (const float*)d_in[23];
    const float* ffn_b2   = (const float*)d_in[24];
    const float* ret_hw   = (const float*)d_in[25];
    const float* ret_hb   = (const float*)d_in[26];
    const float* act_hw   = (const float*)d_in[27];
    const float* act_hb   = (const float*)d_in[28];
    const float* rew_hw   = (const float*)d_in[29];
    const float* rew_hb   = (const float*)d_in[30];

    float *p_patches, *p_x, *p_xn, *p_qkv, *p_o, *p_hid, *p_wtf;
    cudaGetSymbolAddress((void**)&p_patches, g_patches);
    cudaGetSymbolAddress((void**)&p_x, g_x);
    cudaGetSymbolAddress((void**)&p_xn, g_xn);
    cudaGetSymbolAddress((void**)&p_qkv, g_qkv);
    cudaGetSymbolAddress((void**)&p_o, g_o);
    cudaGetSymbolAddress((void**)&p_hid, g_hid);
    cudaGetSymbolAddress((void**)&p_wtf, g_wtf);

    cudaFuncSetAttribute(flash_attn_kernel,
                         cudaFuncAttributeMaxDynamicSharedMemorySize, FA_SMEM_BYTES);
    cudaFuncSetAttribute(mma_gemm_kernel<0, 0>,
                         cudaFuncAttributeMaxDynamicSharedMemorySize, MG_SMEM_BYTES);
    cudaFuncSetAttribute(mma_gemm_kernel<1, 0>,
                         cudaFuncAttributeMaxDynamicSharedMemorySize, MG_SMEM_BYTES);
    cudaFuncSetAttribute(mma_gemm_kernel<2, 1>,
                         cudaFuncAttributeMaxDynamicSharedMemorySize, MG_SMEM_BYTES);

    // 0. weight prep: tf32 round + fragment permutation into scratch
    {
        int t0 = NL * 3 * D * D, t1 = NL * D * D, t2 = NL * DFF * D, t3 = NL * D * DFF;
        wprep_kernel<<<(t0 + 255) / 256, 256>>>(qkv_w,  p_wtf + WTF_QKV, t0);
        wprep_kernel<<<(t1 + 255) / 256, 256>>>(out_w,  p_wtf + WTF_OUT, t1);
        wprep_kernel<<<(t2 + 255) / 256, 256>>>(ffn_w1, p_wtf + WTF_F1,  t2);
        wprep_kernel<<<(t3 + 255) / 256, 256>>>(ffn_w2, p_wtf + WTF_F2,  t3);
    }

    // 1. patchify + patch embed (fp32; K=784 not divisible by 32)
    patchify_kernel<<<(NPATCH * PDIM + 255) / 256, 256>>>(frames);
    gemm_kernel<0><<<dim3(D / 64, NPATCH / 64), 256>>>(p_patches, patch_w, patch_b,
                                                       nullptr, p_o, NPATCH, D, PDIM);
    // 2. assemble sequence with embeddings -> g_x
    assemble_kernel<<<ROWS, 256>>>(rtg, actions, rewards, gids, ret_e, act_e, rew_e,
                                   game_e, pos_e, type_e);

    // 3. transformer layers
    for (int i = 0; i < NL; i++) {
        ln_kernel<<<ROWS, 256>>>(ln1_s + (long)i * D, ln1_b + (long)i * D, p_x, p_xn);
        mma_gemm_kernel<0, 0><<<dim3(3 * D / 64, ROWS / 128), 256, MG_SMEM_BYTES>>>(
            p_xn, p_wtf + WTF_QKV + (long)i * 3 * D * D, qkv_b + (long)i * 3 * D,
            nullptr, p_qkv, ROWS, 3 * D, D);
        flash_attn_kernel<<<dim3(10, B * NH), 256, FA_SMEM_BYTES>>>();
        mma_gemm_kernel<1, 0><<<dim3(D / 64, ROWS / 128), 256, MG_SMEM_BYTES>>>(
            p_o, p_wtf + WTF_OUT + (long)i * D * D, out_b + (long)i * D, p_x, p_x,
            ROWS, D, D);
        ln_kernel<<<ROWS, 256>>>(ln2_s + (long)i * D, ln2_b + (long)i * D, p_x, p_xn);
        mma_gemm_kernel<2, 1><<<dim3(DFF / 64, ROWS / 128), 256, MG_SMEM_BYTES>>>(
            p_xn, p_wtf + WTF_F1 + (long)i * DFF * D, ffn_b1 + (long)i * DFF,
            nullptr, p_hid, ROWS, DFF, D);
        mma_gemm_kernel<1, 0><<<dim3(D / 64, ROWS / 128), 256, MG_SMEM_BYTES>>>(
            p_hid, p_wtf + WTF_F2 + (long)i * D * DFF, ffn_b2 + (long)i * D, p_x, p_x,
            ROWS, D, DFF);
    }

    // 4. heads
    heads_kernel<<<B * T, 256>>>(ret_hw, ret_hb, act_hw, act_hb, rew_hw, rew_hb,
                                 (float*)d_out);
}

// round 11
// speedup vs baseline: 1.0022x; 1.0022x over previous
#include <cuda_runtime.h>
#include <math.h>
#include <stdint.h>

// ---------------------------------------------------------------------------
// MGDT forward. tf32 tensor-core linears (mma.sync m16n8k8) with register-
// prefetch double buffering (single smem buffer, cvt at STS); fused fp32
// flash attention (dynamic smem, prefix-mask); fp32 patch embed.
// Shapes: B=8 T=16 C=4 H=W=84 P=14 NT=36 TPS=39 L=624 D=512 NH=8 DH=64 NL=6
//         DFF=2048 NRET=120 NACT=18 NREW=3
// ---------------------------------------------------------------------------

namespace cfg {
constexpr int B = 8, T = 16, C = 4, H = 84, W = 84, P = 14;
constexpr int NT = 36, TPS = 39, L = 624;
constexpr int D = 512, NH = 8, DH = 64, NL = 6, DFF = 2048;
constexpr int NRET = 120, NACT = 18, NREW = 3;
constexpr int ROWS = B * L;            // 4992
constexpr int NPATCH = B * T * NT;     // 4608
constexpr int PDIM = C * P * P;        // 784
}

using namespace cfg;

// -------------------- scratch (device globals; no runtime alloc) -----------
__device__ float g_patches[NPATCH * PDIM];
__device__ float g_x[ROWS * D];
__device__ float g_xn[ROWS * D];
__device__ float g_qkv[ROWS * 3 * D];
__device__ float g_o[ROWS * D];
__device__ float g_hid[ROWS * DFF];

__device__ __forceinline__ float ftf32(float x) {
    uint32_t u;
    asm("cvt.rna.tf32.f32 %0, %1;" : "=r"(u) : "f"(x));
    return __uint_as_float(u);
}

// -------------------- patch extraction -------------------------------------
__global__ void patchify_kernel(const float* __restrict__ frames) {
    int i = blockIdx.x * blockDim.x + threadIdx.x;
    if (i >= NPATCH * PDIM) return;
    int prow = i / PDIM, f = i - prow * PDIM;
    int bt = prow / NT, n = prow - bt * NT;
    int gy = n / 6, gx = n - gy * 6;
    int c = f / (P * P);
    int r = f - c * P * P;
    int py = r / P, px = r - py * P;
    long src = (((long)bt * C + c) * H + gy * P + py) * W + gx * P + px;
    g_patches[i] = frames[src];
}

// -------------------- fp32 GEMM (patch embed only) --------------------------
template <int EPI>
__global__ void gemm_kernel(const float* __restrict__ A, const float* __restrict__ Wm,
                            const float* __restrict__ bias, const float* __restrict__ res,
                            float* __restrict__ Cmat, int M, int N, int K) {
    __shared__ float As[16][68];
    __shared__ float Bs[16][68];
    int tid = threadIdx.x;
    int bm = blockIdx.y * 64, bn = blockIdx.x * 64;
    int lr = tid >> 2;
    int lk = (tid & 3) * 4;
    int ty = tid >> 4, tx = tid & 15;
    float acc[4][4] = {};
    const float* Aptr = A + (long)(bm + lr) * K + lk;
    const float* Wptr = Wm + (long)(bn + lr) * K + lk;
    for (int k0 = 0; k0 < K; k0 += 16) {
        float4 av = *(const float4*)(Aptr + k0);
        float4 wv = *(const float4*)(Wptr + k0);
        As[lk + 0][lr] = av.x; As[lk + 1][lr] = av.y;
        As[lk + 2][lr] = av.z; As[lk + 3][lr] = av.w;
        Bs[lk + 0][lr] = wv.x; Bs[lk + 1][lr] = wv.y;
        Bs[lk + 2][lr] = wv.z; Bs[lk + 3][lr] = wv.w;
        __syncthreads();
#pragma unroll
        for (int kk = 0; kk < 16; kk++) {
            float4 a4 = *(const float4*)&As[kk][ty * 4];
            float4 b4 = *(const float4*)&Bs[kk][tx * 4];
            float ar[4] = {a4.x, a4.y, a4.z, a4.w};
            float br[4] = {b4.x, b4.y, b4.z, b4.w};
#pragma unroll
            for (int i = 0; i < 4; i++)
#pragma unroll
                for (int j = 0; j < 4; j++)
                    acc[i][j] = fmaf(ar[i], br[j], acc[i][j]);
        }
        __syncthreads();
    }
#pragma unroll
    for (int i = 0; i < 4; i++) {
        int row = bm + ty * 4 + i;
#pragma unroll
        for (int j = 0; j < 4; j++) {
            int col = bn + tx * 4 + j;
            float v = acc[i][j] + bias[col];
            if (EPI == 1) v += res[(long)row * N + col];
            if (EPI == 2) v = 0.5f * v * (1.0f + erff(v * 0.70710678118654752f));
            Cmat[(long)row * N + col] = v;
        }
    }
}

// -------------------- tf32 MMA GEMM, register-prefetch pipeline -------------
// C = A(MxK) @ W(NxK)^T + bias. Block 128x64, 8 warps (4M x 2N), warp tile
// 32x32, k-tile 32. Single smem buffer (27.6KB static); next k-tile is
// prefetched into registers during compute (LDG latency overlapped), cvt to
// tf32 at STS time (identical numerics to the 3615us baseline).
// EPI: 0 none, 1 residual add, 2 exact GELU
template <int EPI>
__global__ __launch_bounds__(256) void mma_gemm_kernel(
        const float* __restrict__ A, const float* __restrict__ Wm,
        const float* __restrict__ bias, const float* __restrict__ res,
        float* __restrict__ Cmat, int M, int N, int K) {
    __shared__ float As[128][36];
    __shared__ float Bs[64][36];
    int tid = threadIdx.x;
    int bm = blockIdx.y * 128, bn = blockIdx.x * 64;
    int warp = tid >> 5, lane = tid & 31;
    int grp = lane >> 2, qd = lane & 3;
    int wm0 = (warp >> 1) * 32, wn0 = (warp & 1) * 32;
    float acc[2][4][4] = {};

    int arow = tid >> 3;             // 0..31
    int af4 = (tid & 7) * 4;         // 0,4,..,28
    int b_r0 = tid >> 3;             // 0..31   (B rows: idx>>3)
    int b_r1 = (tid + 256) >> 3;     // 32..63
    int b_f4 = (tid & 7) * 4;

    float4 pa[4], pb[2];
    auto gload = [&](int k0) {
#pragma unroll
        for (int i = 0; i < 4; i++)
            pa[i] = *(const float4*)(A + (long)(bm + arow + 32 * i) * K + k0 + af4);
        pb[0] = *(const float4*)(Wm + (long)(bn + b_r0) * K + k0 + b_f4);
        pb[1] = *(const float4*)(Wm + (long)(bn + b_r1) * K + k0 + b_f4);
    };

    int KT = K / 32;
    gload(0);
    for (int kt = 0; kt < KT; kt++) {
        // commit prefetched tile to smem (tf32 round at STS, as baseline)
#pragma unroll
        for (int i = 0; i < 4; i++) {
            int r = arow + 32 * i;
            As[r][af4 + 0] = ftf32(pa[i].x);
            As[r][af4 + 1] = ftf32(pa[i].y);
            As[r][af4 + 2] = ftf32(pa[i].z);
            As[r][af4 + 3] = ftf32(pa[i].w);
        }
        Bs[b_r0][b_f4 + 0] = ftf32(pb[0].x);
        Bs[b_r0][b_f4 + 1] = ftf32(pb[0].y);
        Bs[b_r0][b_f4 + 2] = ftf32(pb[0].z);
        Bs[b_r0][b_f4 + 3] = ftf32(pb[0].w);
        Bs[b_r1][b_f4 + 0] = ftf32(pb[1].x);
        Bs[b_r1][b_f4 + 1] = ftf32(pb[1].y);
        Bs[b_r1][b_f4 + 2] = ftf32(pb[1].z);
        Bs[b_r1][b_f4 + 3] = ftf32(pb[1].w);
        __syncthreads();

        // prefetch next k-tile into registers; LDG latency hides under MMAs
        if (kt + 1 < KT) gload((kt + 1) * 32);

#pragma unroll
        for (int ks = 0; ks < 4; ks++) {
            uint32_t a[2][4];
            uint32_t b[4][2];
#pragma unroll
            for (int mi = 0; mi < 2; mi++) {
                int r = wm0 + mi * 16 + grp;
                int kk = ks * 8 + qd;
                a[mi][0] = __float_as_uint(As[r][kk]);
                a[mi][1] = __float_as_uint(As[r + 8][kk]);
                a[mi][2] = __float_as_uint(As[r][kk + 4]);
                a[mi][3] = __float_as_uint(As[r + 8][kk + 4]);
            }
#pragma unroll
            for (int ni = 0; ni < 4; ni++) {
                int c = wn0 + ni * 8 + grp;
                int kk = ks * 8 + qd;
                b[ni][0] = __float_as_uint(Bs[c][kk]);
                b[ni][1] = __float_as_uint(Bs[c][kk + 4]);
            }
#pragma unroll
            for (int mi = 0; mi < 2; mi++)
#pragma unroll
                for (int ni = 0; ni < 4; ni++)
                    asm volatile(
                        "mma.sync.aligned.m16n8k8.row.col.f32.tf32.tf32.f32 "
                        "{%0,%1,%2,%3},{%4,%5,%6,%7},{%8,%9},{%0,%1,%2,%3};\n"
                        : "+f"(acc[mi][ni][0]), "+f"(acc[mi][ni][1]),
                          "+f"(acc[mi][ni][2]), "+f"(acc[mi][ni][3])
                        : "r"(a[mi][0]), "r"(a[mi][1]), "r"(a[mi][2]), "r"(a[mi][3]),
                          "r"(b[ni][0]), "r"(b[ni][1]));
        }
        __syncthreads();
    }
#pragma unroll
    for (int mi = 0; mi < 2; mi++) {
#pragma unroll
        for (int ni = 0; ni < 4; ni++) {
            int r = bm + wm0 + mi * 16 + grp;
            int c = bn + wn0 + ni * 8 + 2 * qd;
            float b0 = bias[c], b1 = bias[c + 1];
#pragma unroll
            for (int h = 0; h < 2; h++) {
                int row = r + 8 * h;
                float v0 = acc[mi][ni][2 * h + 0] + b0;
                float v1 = acc[mi][ni][2 * h + 1] + b1;
                if (EPI == 1) {
                    const float2 rr = *(const float2*)(res + (long)row * N + c);
                    v0 += rr.x; v1 += rr.y;
                }
                if (EPI == 2) {
                    v0 = 0.5f * v0 * (1.0f + erff(v0 * 0.70710678118654752f));
                    v1 = 0.5f * v1 * (1.0f + erff(v1 * 0.70710678118654752f));
                }
                *(float2*)(Cmat + (long)row * N + c) = make_float2(v0, v1);
            }
        }
    }
}

// -------------------- layernorm ---------------------------------------------
__global__ void ln_kernel(const float* __restrict__ s, const float* __restrict__ bta,
                          const float* __restrict__ in, float* __restrict__ out) {
    int row = blockIdx.x;
    const float* x = in + (long)row * D;
    int tid = threadIdx.x;
    float v0 = x[tid], v1 = x[tid + 256];
    __shared__ float red[256];
    red[tid] = v0 + v1;
    __syncthreads();
    for (int st = 128; st > 0; st >>= 1) {
        if (tid < st) red[tid] += red[tid + st];
        __syncthreads();
    }
    float mu = red[0] * (1.0f / 512.0f);
    __syncthreads();
    float d0 = v0 - mu, d1 = v1 - mu;
    red[tid] = d0 * d0 + d1 * d1;
    __syncthreads();
    for (int st = 128; st > 0; st >>= 1) {
        if (tid < st) red[tid] += red[tid + st];
        __syncthreads();
    }
    float rstd = rsqrtf(red[0] * (1.0f / 512.0f) + 1e-5f);
    float* o = out + (long)row * D;
    o[tid]       = d0 * rstd * s[tid]       + bta[tid];
    o[tid + 256] = d1 * rstd * s[tid + 256] + bta[tid + 256];
}

// -------------------- token assembly ----------------------------------------
__global__ void assemble_kernel(const int* __restrict__ rtg, const int* __restrict__ act,
                                const int* __restrict__ rew, const int* __restrict__ gid,
                                const float* __restrict__ ret_e, const float* __restrict__ act_e,
                                const float* __restrict__ rew_e, const float* __restrict__ game_e,
                                const float* __restrict__ pos_e, const float* __restrict__ type_e) {
    int row = blockIdx.x;
    int b = row / L, l = row - b * L;
    int t = l / TPS, off = l - t * TPS;
    int tid = threadIdx.x;
    const float* src;
    int typ;
    if (off < NT)           { src = g_o + ((long)(b * T + t) * NT + off) * D; typ = 0; }
    else if (off == NT)     { src = ret_e + (long)rtg[b * T + t] * D;        typ = 1; }
    else if (off == NT + 1) { src = act_e + (long)act[b * T + t] * D;        typ = 2; }
    else                    { src = rew_e + (long)rew[b * T + t] * D;        typ = 3; }
    int g = gid[b];
    float* dst = g_x + (long)row * D;
    for (int d = tid; d < D; d += blockDim.x)
        dst[d] = src[d] + pos_e[(long)l * D + d] + type_e[(long)typ * D + d]
               + game_e[(long)g * D + d];
}

// -------------------- fused flash attention (fp32, dynamic smem) ------------
// Mask is a per-row PREFIX: allowed(q,k) <=> k <= klim(q); klim monotone in q.
constexpr int FA_TILE_FLOATS = 64 * 68;
constexpr int FA_SMEM_BYTES = 4 * FA_TILE_FLOATS * 4;

__global__ __launch_bounds__(256) void flash_attn_kernel() {
    extern __shared__ float fa_smem[];
    float (*Qs)[68] = (float(*)[68])(fa_smem);                      // [d][q]
    float (*Ks)[68] = (float(*)[68])(fa_smem + FA_TILE_FLOATS);     // [d][k]
    float (*Vs)[68] = (float(*)[68])(fa_smem + 2 * FA_TILE_FLOATS); // [k][d]
    float (*Ps)[68] = (float(*)[68])(fa_smem + 3 * FA_TILE_FLOATS); // [k][q]
    int bh = blockIdx.y;
    int b = bh >> 3, h = bh & 7;
    int q0 = blockIdx.x * 64;
    int tid = threadIdx.x;
    int ty = tid >> 4, tx = tid & 15;
    const float* qbase = g_qkv + (long)b * L * (3 * D) + h * DH;
    const float* kbase = qbase + D;
    const float* vbase = qbase + 2 * D;

#pragma unroll
    for (int r = 0; r < 4; r++) {
        int c = r * 256 + tid;
        int row = c >> 4;
        int d4 = (c & 15) * 4;
        float4 qv = make_float4(0, 0, 0, 0);
        int gq = q0 + row;
        if (gq < L) qv = *(const float4*)(qbase + (long)gq * (3 * D) + d4);
        Qs[d4 + 0][row] = qv.x; Qs[d4 + 1][row] = qv.y;
        Qs[d4 + 2][row] = qv.z; Qs[d4 + 3][row] = qv.w;
    }

    float m[4], l[4], acc[4][4];
#pragma unroll
    for (int i = 0; i < 4; i++) {
        m[i] = -1e30f; l[i] = 0.0f;
#pragma unroll
        for (int j = 0; j < 4; j++) acc[i][j] = 0.0f;
    }

    int klim[4];
#pragma unroll
    for (int i = 0; i < 4; i++) {
        int q = q0 + ty * 4 + i;
        if (q >= L) klim[i] = 0;
        else {
            int st = q / TPS, off = q - st * TPS;
            klim[i] = (off < NT) ? st * TPS + NT - 1 : q;
        }
    }
    int qlast = min(q0 + 63, L - 1);
    int stl = qlast / TPS, offl = qlast - stl * TPS;
    int klim_max = (offl < NT) ? stl * TPS + NT - 1 : qlast;
    int nkt = klim_max / 64 + 1;

    for (int kt = 0; kt < nkt; kt++) {
        int k0 = kt * 64;
#pragma unroll
        for (int r = 0; r < 4; r++) {
            int c = r * 256 + tid;
            int row = c >> 4;
            int d4 = (c & 15) * 4;
            int gk = k0 + row;
            float4 kv = make_float4(0, 0, 0, 0), vv = make_float4(0, 0, 0, 0);
            if (gk < L) {
                kv = *(const float4*)(kbase + (long)gk * (3 * D) + d4);
                vv = *(const float4*)(vbase + (long)gk * (3 * D) + d4);
            }
            Ks[d4 + 0][row] = kv.x; Ks[d4 + 1][row] = kv.y;
            Ks[d4 + 2][row] = kv.z; Ks[d4 + 3][row] = kv.w;
            *(float4*)&Vs[row][d4] = vv;
        }
        __syncthreads();

        float s[4][4] = {};
#pragma unroll 8
        for (int d = 0; d < 64; d++) {
            float4 a4 = *(const float4*)&Qs[d][ty * 4];
            float4 b4 = *(const float4*)&Ks[d][tx * 4];
            float ar[4] = {a4.x, a4.y, a4.z, a4.w};
            float br[4] = {b4.x, b4.y, b4.z, b4.w};
#pragma unroll
            for (int i = 0; i < 4; i++)
#pragma unroll
                for (int j = 0; j < 4; j++)
                    s[i][j] = fmaf(ar[i], br[j], s[i][j]);
        }

#pragma unroll
        for (int i = 0; i < 4; i++) {
            float rm = -1e30f;
#pragma unroll
            for (int j = 0; j < 4; j++) {
                int k = k0 + tx * 4 + j;
                s[i][j] = (k <= klim[i]) ? s[i][j] * 0.125f : -1e30f;
                rm = fmaxf(rm, s[i][j]);
            }
#pragma unroll
            for (int w = 1; w < 16; w <<= 1)
                rm = fmaxf(rm, __shfl_xor_sync(0xffffffffu, rm, w));
            float mn = fmaxf(m[i], rm);
            float corr = __expf(m[i] - mn);
            float rs = 0.0f;
#pragma unroll
            for (int j = 0; j < 4; j++) {
                float p = __expf(s[i][j] - mn);
                s[i][j] = p;
                rs += p;
            }
#pragma unroll
            for (int w = 1; w < 16; w <<= 1)
                rs += __shfl_xor_sync(0xffffffffu, rs, w);
            l[i] = l[i] * corr + rs;
            m[i] = mn;
#pragma unroll
            for (int j = 0; j < 4; j++) acc[i][j] *= corr;
        }

        __syncthreads();
#pragma unroll
        for (int j = 0; j < 4; j++) {
            float4 pv = make_float4(s[0][j], s[1][j], s[2][j], s[3][j]);
            *(float4*)&Ps[tx * 4 + j][ty * 4] = pv;
        }
        __syncthreads();

#pragma unroll 8
        for (int k = 0; k < 64; k++) {
            float4 a4 = *(const float4*)&Ps[k][ty * 4];
            float4 b4 = *(const float4*)&Vs[k][tx * 4];
            float ar[4] = {a4.x, a4.y, a4.z, a4.w};
            float br[4] = {b4.x, b4.y, b4.z, b4.w};
#pragma unroll
            for (int i = 0; i < 4; i++)
#pragma unroll
                for (int j = 0; j < 4; j++)
                    acc[i][j] = fmaf(ar[i], br[j], acc[i][j]);
        }
        __syncthreads();
    }

    float* obase = g_o + (long)b * L * D + h * DH;
#pragma unroll
    for (int i = 0; i < 4; i++) {
        int q = q0 + ty * 4 + i;
        if (q >= L) continue;
        float inv = 1.0f / l[i];
        float4 o4 = make_float4(acc[i][0] * inv, acc[i][1] * inv,
                                acc[i][2] * inv, acc[i][3] * inv);
        *(float4*)(obase + (long)q * D + tx * 4) = o4;
    }
}

// -------------------- heads -------------------------------------------------
__global__ void heads_kernel(const float* __restrict__ rw, const float* __restrict__ rb,
                             const float* __restrict__ aw, const float* __restrict__ ab,
                             const float* __restrict__ ww, const float* __restrict__ wb,
                             float* __restrict__ out) {
    int bt = blockIdx.x;
    int b = bt / T, t = bt - b * T;
    __shared__ float hsh[3][D];
    int tid = threadIdx.x;
    const float* base = g_x + ((long)b * L + (long)t * TPS + (NT - 1)) * D;
    for (int d = tid; d < 3 * D; d += blockDim.x)
        hsh[d / D][d % D] = base[d];
    __syncthreads();
    if (tid < NRET) {
        float s = rb[tid];
        for (int k = 0; k < D; k++) s = fmaf(hsh[0][k], rw[(long)tid * D + k], s);
        out[(long)bt * NRET + tid] = s;
    } else if (tid < NRET + NACT) {
        int j = tid - NRET;
        float s = ab[j];
        for (int k = 0; k < D; k++) s = fmaf(hsh[1][k], aw[(long)j * D + k], s);
        out[(long)B * T * NRET + (long)bt * NACT + j] = s;
    } else if (tid < NRET + NACT + NREW) {
        int j = tid - NRET - NACT;
        float s = wb[j];
        for (int k = 0; k < D; k++) s = fmaf(hsh[2][k], ww[(long)j * D + k], s);
        out[(long)B * T * (NRET + NACT) + (long)bt * NREW + j] = s;
    }
}

// -------------------- launch ------------------------------------------------
extern "C" void kernel_launch(void* const* d_in, const int* in_sizes, int n_in,
                              void* d_out, int out_size) {
    const float* frames   = (const float*)d_in[0];
    const int*   rtg      = (const int*)d_in[1];
    const int*   actions  = (const int*)d_in[2];
    const int*   rewards  = (const int*)d_in[3];
    const int*   gids     = (const int*)d_in[4];
    const float* patch_w  = (const float*)d_in[5];
    const float* patch_b  = (const float*)d_in[6];
    const float* ret_e    = (const float*)d_in[7];
    const float* act_e    = (const float*)d_in[8];
    const float* rew_e    = (const float*)d_in[9];
    const float* game_e   = (const float*)d_in[10];
    const float* pos_e    = (const float*)d_in[11];
    const float* type_e   = (const float*)d_in[12];
    const float* qkv_w    = (const float*)d_in[13];
    const float* qkv_b    = (const float*)d_in[14];
    const float* out_w    = (const float*)d_in[15];
    const float* out_b    = (const float*)d_in[16];
    const float* ln1_s    = (const float*)d_in[17];
    const float* ln1_b    = (const float*)d_in[18];
    const float* ln2_s    = (const float*)d_in[19];
    const float* ln2_b    = (const float*)d_in[20];
    const float* ffn_w1   = (const float*)d_in[21];
    const float* ffn_b1   = (const float*)d_in[22];
    const float* ffn_w2   = (const float*)d_in[23];
    const float* ffn_b2   = (const float*)d_in[24];
    const float* ret_hw   = (const float*)d_in[25];
    const float* ret_hb   = (const float*)d_in[26];
    const float* act_hw   = (const float*)d_in[27];
    const float* act_hb   = (const float*)d_in[28];
    const float* rew_hw   = (const float*)d_in[29];
    const float* rew_hb   = (const float*)d_in[30];

    float *p_patches, *p_x, *p_xn, *p_qkv, *p_o, *p_hid;
    cudaGetSymbolAddress((void**)&p_patches, g_patches);
    cudaGetSymbolAddress((void**)&p_x, g_x);
    cudaGetSymbolAddress((void**)&p_xn, g_xn);
    cudaGetSymbolAddress((void**)&p_qkv, g_qkv);
    cudaGetSymbolAddress((void**)&p_o, g_o);
    cudaGetSymbolAddress((void**)&p_hid, g_hid);

    cudaFuncSetAttribute(flash_attn_kernel,
                         cudaFuncAttributeMaxDynamicSharedMemorySize,
                         FA_SMEM_BYTES);

    // 1. patchify + patch embed (fp32; K=784 not divisible by 32)
    patchify_kernel<<<(NPATCH * PDIM + 255) / 256, 256>>>(frames);
    gemm_kernel<0><<<dim3(D / 64, NPATCH / 64), 256>>>(p_patches, patch_w, patch_b,
                                                       nullptr, p_o, NPATCH, D, PDIM);
    // 2. assemble sequence with embeddings -> g_x
    assemble_kernel<<<ROWS, 256>>>(rtg, actions, rewards, gids, ret_e, act_e, rew_e,
                                   game_e, pos_e, type_e);

    // 3. transformer layers
    for (int i = 0; i < NL; i++) {
        ln_kernel<<<ROWS, 256>>>(ln1_s + (long)i * D, ln1_b + (long)i * D, p_x, p_xn);
        mma_gemm_kernel<0><<<dim3(3 * D / 64, ROWS / 128), 256>>>(
            p_xn, qkv_w + (long)i * 3 * D * D, qkv_b + (long)i * 3 * D,
            nullptr, p_qkv, ROWS, 3 * D, D);
        flash_attn_kernel<<<dim3(10, B * NH), 256, FA_SMEM_BYTES>>>();
        mma_gemm_kernel<1><<<dim3(D / 64, ROWS / 128), 256>>>(
            p_o, out_w + (long)i * D * D, out_b + (long)i * D, p_x, p_x, ROWS, D, D);
        ln_kernel<<<ROWS, 256>>>(ln2_s + (long)i * D, ln2_b + (long)i * D, p_x, p_xn);
        mma_gemm_kernel<2><<<dim3(DFF / 64, ROWS / 128), 256>>>(
            p_xn, ffn_w1 + (long)i * DFF * D, ffn_b1 + (long)i * DFF,
            nullptr, p_hid, ROWS, DFF, D);
        mma_gemm_kernel<1><<<dim3(D / 64, ROWS / 128), 256>>>(
            p_hid, ffn_w2 + (long)i * D * DFF, ffn_b2 + (long)i * D, p_x, p_x,
            ROWS, D, DFF);
    }

    // 4. heads
    heads_kernel<<<B * T, 256>>>(ret_hw, ret_hb, act_hw, act_hb, rew_hw, rew_hb,
                                 (float*)d_out);
}

// round 13
// speedup vs baseline: 1.0917x; 1.0893x over previous
#include <cuda_runtime.h>
#include <math.h>
#include <stdint.h>

// ---------------------------------------------------------------------------
// MGDT forward. tf32 tensor-core linears (mma.sync m16n8k8): operands are
// pre-rounded to tf32 in gmem (coalesced weight-prep + producer-side rounding
// at ln/flash/gelu stores), cp.async double-buffered mainloop with ZERO cvts
// and R7's register footprint. Fused fp32 flash attention (prefix mask).
// Shapes: B=8 T=16 C=4 H=W=84 P=14 NT=36 TPS=39 L=624 D=512 NH=8 DH=64 NL=6
//         DFF=2048 NRET=120 NACT=18 NREW=3
// ---------------------------------------------------------------------------

namespace cfg {
constexpr int B = 8, T = 16, C = 4, H = 84, W = 84, P = 14;
constexpr int NT = 36, TPS = 39, L = 624;
constexpr int D = 512, NH = 8, DH = 64, NL = 6, DFF = 2048;
constexpr int NRET = 120, NACT = 18, NREW = 3;
constexpr int ROWS = B * L;            // 4992
constexpr int NPATCH = B * T * NT;     // 4608
constexpr int PDIM = C * P * P;        // 784
}

using namespace cfg;

// tf32-rounded weight scratch offsets (contiguous layout, no permutation)
constexpr long WTF_QKV = 0;
constexpr long WTF_OUT = (long)NL * 3 * D * D;
constexpr long WTF_F1  = WTF_OUT + (long)NL * D * D;
constexpr long WTF_F2  = WTF_F1 + (long)NL * DFF * D;
constexpr long WTF_TOTAL = WTF_F2 + (long)NL * D * DFF;

// -------------------- scratch (device globals; no runtime alloc) -----------
__device__ float g_patches[NPATCH * PDIM];
__device__ float g_x[ROWS * D];        // residual stream (raw fp32)
__device__ float g_xn[ROWS * D];       // tf32-rounded (GEMM-A only)
__device__ float g_qkv[ROWS * 3 * D];  // raw fp32 (flash input)
__device__ float g_o[ROWS * D];        // patch path raw; attn out tf32-rounded
__device__ float g_hid[ROWS * DFF];    // tf32-rounded (GEMM-A only)
__device__ float g_wtf[WTF_TOTAL];     // tf32-rounded weights

__device__ __forceinline__ float ftf32(float x) {
    uint32_t u;
    asm("cvt.rna.tf32.f32 %0, %1;" : "=r"(u) : "f"(x));
    return __uint_as_float(u);
}

// -------------------- weight prep: coalesced tf32 round ---------------------
__global__ void wprep_kernel(const float* __restrict__ src, float* __restrict__ dst,
                             int total) {
    int i = blockIdx.x * blockDim.x + threadIdx.x;
    if (i < total) dst[i] = ftf32(src[i]);
}

// -------------------- patch extraction -------------------------------------
__global__ void patchify_kernel(const float* __restrict__ frames) {
    int i = blockIdx.x * blockDim.x + threadIdx.x;
    if (i >= NPATCH * PDIM) return;
    int prow = i / PDIM, f = i - prow * PDIM;
    int bt = prow / NT, n = prow - bt * NT;
    int gy = n / 6, gx = n - gy * 6;
    int c = f / (P * P);
    int r = f - c * P * P;
    int py = r / P, px = r - py * P;
    long src = (((long)bt * C + c) * H + gy * P + py) * W + gx * P + px;
    g_patches[i] = frames[src];
}

// -------------------- fp32 GEMM (patch embed only) --------------------------
template <int EPI>
__global__ void gemm_kernel(const float* __restrict__ A, const float* __restrict__ Wm,
                            const float* __restrict__ bias, const float* __restrict__ res,
                            float* __restrict__ Cmat, int M, int N, int K) {
    __shared__ float As[16][68];
    __shared__ float Bs[16][68];
    int tid = threadIdx.x;
    int bm = blockIdx.y * 64, bn = blockIdx.x * 64;
    int lr = tid >> 2;
    int lk = (tid & 3) * 4;
    int ty = tid >> 4, tx = tid & 15;
    float acc[4][4] = {};
    const float* Aptr = A + (long)(bm + lr) * K + lk;
    const float* Wptr = Wm + (long)(bn + lr) * K + lk;
    for (int k0 = 0; k0 < K; k0 += 16) {
        float4 av = *(const float4*)(Aptr + k0);
        float4 wv = *(const float4*)(Wptr + k0);
        As[lk + 0][lr] = av.x; As[lk + 1][lr] = av.y;
        As[lk + 2][lr] = av.z; As[lk + 3][lr] = av.w;
        Bs[lk + 0][lr] = wv.x; Bs[lk + 1][lr] = wv.y;
        Bs[lk + 2][lr] = wv.z; Bs[lk + 3][lr] = wv.w;
        __syncthreads();
#pragma unroll
        for (int kk = 0; kk < 16; kk++) {
            float4 a4 = *(const float4*)&As[kk][ty * 4];
            float4 b4 = *(const float4*)&Bs[kk][tx * 4];
            float ar[4] = {a4.x, a4.y, a4.z, a4.w};
            float br[4] = {b4.x, b4.y, b4.z, b4.w};
#pragma unroll
            for (int i = 0; i < 4; i++)
#pragma unroll
                for (int j = 0; j < 4; j++)
                    acc[i][j] = fmaf(ar[i], br[j], acc[i][j]);
        }
        __syncthreads();
    }
#pragma unroll
    for (int i = 0; i < 4; i++) {
        int row = bm + ty * 4 + i;
#pragma unroll
        for (int j = 0; j < 4; j++) {
            int col = bn + tx * 4 + j;
            float v = acc[i][j] + bias[col];
            if (EPI == 1) v += res[(long)row * N + col];
            if (EPI == 2) v = 0.5f * v * (1.0f + erff(v * 0.70710678118654752f));
            Cmat[(long)row * N + col] = v;
        }
    }
}

// -------------------- tf32 MMA GEMM, cp.async, pre-rounded operands ---------
// C = A(MxK) @ W(NxK)^T + bias. A and W are already tf32-rounded in gmem ->
// mainloop has no cvts. Block 128x64, 8 warps (4M x 2N), warp tile 32x32,
// k-tile 32, 2-stage cp.async pipeline, scalar-LDS fragments (R7 layout).
// EPI: 0 none (raw store), 1 residual add (raw store), 2 GELU (tf32 store,
// since g_hid feeds ffn2 as A).
constexpr int MG_STAGE_FLOATS = 128 * 36 + 64 * 36;      // 6912
constexpr int MG_SMEM_BYTES = 2 * MG_STAGE_FLOATS * 4;   // 55296

template <int EPI>
__global__ __launch_bounds__(256) void mma_gemm_kernel(
        const float* __restrict__ A, const float* __restrict__ Wm,
        const float* __restrict__ bias, const float* __restrict__ res,
        float* __restrict__ Cmat, int M, int N, int K) {
    extern __shared__ float mg_smem[];
    int tid = threadIdx.x;
    int bm = blockIdx.y * 128, bn = blockIdx.x * 64;
    int warp = tid >> 5, lane = tid & 31;
    int grp = lane >> 2, qd = lane & 3;
    int wm0 = (warp >> 1) * 32, wn0 = (warp & 1) * 32;
    float acc[2][4][4] = {};

    int arow = tid >> 3;             // 0..31
    int af4 = (tid & 7) * 4;         // 0,4,..,28

    auto prefetch = [&](int k0, int s) {
        float* As = mg_smem + s * MG_STAGE_FLOATS;
        float* Bs = As + 128 * 36;
#pragma unroll
        for (int i = 0; i < 4; i++) {
            int r = arow + 32 * i;
            uint32_t dst = (uint32_t)__cvta_generic_to_shared(&As[r * 36 + af4]);
            const float* src = A + (long)(bm + r) * K + k0 + af4;
            asm volatile("cp.async.cg.shared.global [%0], [%1], 16;\n"
                         :: "r"(dst), "l"(src));
        }
#pragma unroll
        for (int i = 0; i < 2; i++) {
            int idx = tid + 256 * i;
            int r = idx >> 3;
            int f4 = (idx & 7) * 4;
            uint32_t dst = (uint32_t)__cvta_generic_to_shared(&Bs[r * 36 + f4]);
            const float* src = Wm + (long)(bn + r) * K + k0 + f4;
            asm volatile("cp.async.cg.shared.global [%0], [%1], 16;\n"
                         :: "r"(dst), "l"(src));
        }
        asm volatile("cp.async.commit_group;\n");
    };

    int KT = K / 32;
    prefetch(0, 0);
    for (int kt = 0; kt < KT; kt++) {
        if (kt + 1 < KT) {
            prefetch((kt + 1) * 32, (kt + 1) & 1);
            asm volatile("cp.async.wait_group 1;\n");
        } else {
            asm volatile("cp.async.wait_group 0;\n");
        }
        __syncthreads();
        const float* As = mg_smem + (kt & 1) * MG_STAGE_FLOATS;
        const float* Bs = As + 128 * 36;
#pragma unroll
        for (int ks = 0; ks < 4; ks++) {
            uint32_t a[2][4];
            uint32_t b[4][2];
#pragma unroll
            for (int mi = 0; mi < 2; mi++) {
                int r = wm0 + mi * 16 + grp;
                int kk = ks * 8 + qd;
                a[mi][0] = __float_as_uint(As[r * 36 + kk]);
                a[mi][1] = __float_as_uint(As[(r + 8) * 36 + kk]);
                a[mi][2] = __float_as_uint(As[r * 36 + kk + 4]);
                a[mi][3] = __float_as_uint(As[(r + 8) * 36 + kk + 4]);
            }
#pragma unroll
            for (int ni = 0; ni < 4; ni++) {
                int c = wn0 + ni * 8 + grp;
                int kk = ks * 8 + qd;
                b[ni][0] = __float_as_uint(Bs[c * 36 + kk]);
                b[ni][1] = __float_as_uint(Bs[c * 36 + kk + 4]);
            }
#pragma unroll
            for (int mi = 0; mi < 2; mi++)
#pragma unroll
                for (int ni = 0; ni < 4; ni++)
                    asm volatile(
                        "mma.sync.aligned.m16n8k8.row.col.f32.tf32.tf32.f32 "
                        "{%0,%1,%2,%3},{%4,%5,%6,%7},{%8,%9},{%0,%1,%2,%3};\n"
                        : "+f"(acc[mi][ni][0]), "+f"(acc[mi][ni][1]),
                          "+f"(acc[mi][ni][2]), "+f"(acc[mi][ni][3])
                        : "r"(a[mi][0]), "r"(a[mi][1]), "r"(a[mi][2]), "r"(a[mi][3]),
                          "r"(b[ni][0]), "r"(b[ni][1]));
        }
        __syncthreads();
    }
#pragma unroll
    for (int mi = 0; mi < 2; mi++) {
#pragma unroll
        for (int ni = 0; ni < 4; ni++) {
            int r = bm + wm0 + mi * 16 + grp;
            int c = bn + wn0 + ni * 8 + 2 * qd;
            float b0 = bias[c], b1 = bias[c + 1];
#pragma unroll
            for (int h = 0; h < 2; h++) {
                int row = r + 8 * h;
                float v0 = acc[mi][ni][2 * h + 0] + b0;
                float v1 = acc[mi][ni][2 * h + 1] + b1;
                if (EPI == 1) {
                    const float2 rr = *(const float2*)(res + (long)row * N + c);
                    v0 += rr.x; v1 += rr.y;
                }
                if (EPI == 2) {
                    v0 = 0.5f * v0 * (1.0f + erff(v0 * 0.70710678118654752f));
                    v1 = 0.5f * v1 * (1.0f + erff(v1 * 0.70710678118654752f));
                    v0 = ftf32(v0);   // g_hid is GEMM-A of ffn2
                    v1 = ftf32(v1);
                }
                *(float2*)(Cmat + (long)row * N + c) = make_float2(v0, v1);
            }
        }
    }
}

// -------------------- layernorm (tf32-rounded output: GEMM-A only) ----------
__global__ void ln_kernel(const float* __restrict__ s, const float* __restrict__ bta,
                          const float* __restrict__ in, float* __restrict__ out) {
    int row = blockIdx.x;
    const float* x = in + (long)row * D;
    int tid = threadIdx.x;
    float v0 = x[tid], v1 = x[tid + 256];
    __shared__ float red[256];
    red[tid] = v0 + v1;
    __syncthreads();
    for (int st = 128; st > 0; st >>= 1) {
        if (tid < st) red[tid] += red[tid + st];
        __syncthreads();
    }
    float mu = red[0] * (1.0f / 512.0f);
    __syncthreads();
    float d0 = v0 - mu, d1 = v1 - mu;
    red[tid] = d0 * d0 + d1 * d1;
    __syncthreads();
    for (int st = 128; st > 0; st >>= 1) {
        if (tid < st) red[tid] += red[tid + st];
        __syncthreads();
    }
    float rstd = rsqrtf(red[0] * (1.0f / 512.0f) + 1e-5f);
    float* o = out + (long)row * D;
    o[tid]       = ftf32(d0 * rstd * s[tid]       + bta[tid]);
    o[tid + 256] = ftf32(d1 * rstd * s[tid + 256] + bta[tid + 256]);
}

// -------------------- token assembly ----------------------------------------
__global__ void assemble_kernel(const int* __restrict__ rtg, const int* __restrict__ act,
                                const int* __restrict__ rew, const int* __restrict__ gid,
                                const float* __restrict__ ret_e, const float* __restrict__ act_e,
                                const float* __restrict__ rew_e, const float* __restrict__ game_e,
                                const float* __restrict__ pos_e, const float* __restrict__ type_e) {
    int row = blockIdx.x;
    int b = row / L, l = row - b * L;
    int t = l / TPS, off = l - t * TPS;
    int tid = threadIdx.x;
    const float* src;
    int typ;
    if (off < NT)           { src = g_o + ((long)(b * T + t) * NT + off) * D; typ = 0; }
    else if (off == NT)     { src = ret_e + (long)rtg[b * T + t] * D;        typ = 1; }
    else if (off == NT + 1) { src = act_e + (long)act[b * T + t] * D;        typ = 2; }
    else                    { src = rew_e + (long)rew[b * T + t] * D;        typ = 3; }
    int g = gid[b];
    float* dst = g_x + (long)row * D;
    for (int d = tid; d < D; d += blockDim.x)
        dst[d] = src[d] + pos_e[(long)l * D + d] + type_e[(long)typ * D + d]
               + game_e[(long)g * D + d];
}

// -------------------- fused flash attention (fp32, dynamic smem) ------------
// Mask is a per-row PREFIX: allowed(q,k) <=> k <= klim(q); klim monotone in q.
// Epilogue writes g_o tf32-rounded (consumed only by out-proj GEMM as A).
constexpr int FA_TILE_FLOATS = 64 * 68;
constexpr int FA_SMEM_BYTES = 4 * FA_TILE_FLOATS * 4;

__global__ __launch_bounds__(256) void flash_attn_kernel() {
    extern __shared__ float fa_smem[];
    float (*Qs)[68] = (float(*)[68])(fa_smem);                      // [d][q]
    float (*Ks)[68] = (float(*)[68])(fa_smem + FA_TILE_FLOATS);     // [d][k]
    float (*Vs)[68] = (float(*)[68])(fa_smem + 2 * FA_TILE_FLOATS); // [k][d]
    float (*Ps)[68] = (float(*)[68])(fa_smem + 3 * FA_TILE_FLOATS); // [k][q]
    int bh = blockIdx.y;
    int b = bh >> 3, h = bh & 7;
    int q0 = blockIdx.x * 64;
    int tid = threadIdx.x;
    int ty = tid >> 4, tx = tid & 15;
    const float* qbase = g_qkv + (long)b * L * (3 * D) + h * DH;
    const float* kbase = qbase + D;
    const float* vbase = qbase + 2 * D;

#pragma unroll
    for (int r = 0; r < 4; r++) {
        int c = r * 256 + tid;
        int row = c >> 4;
        int d4 = (c & 15) * 4;
        float4 qv = make_float4(0, 0, 0, 0);
        int gq = q0 + row;
        if (gq < L) qv = *(const float4*)(qbase + (long)gq * (3 * D) + d4);
        Qs[d4 + 0][row] = qv.x; Qs[d4 + 1][row] = qv.y;
        Qs[d4 + 2][row] = qv.z; Qs[d4 + 3][row] = qv.w;
    }

    float m[4], l[4], acc[4][4];
#pragma unroll
    for (int i = 0; i < 4; i++) {
        m[i] = -1e30f; l[i] = 0.0f;
#pragma unroll
        for (int j = 0; j < 4; j++) acc[i][j] = 0.0f;
    }

    int klim[4];
#pragma unroll
    for (int i = 0; i < 4; i++) {
        int q = q0 + ty * 4 + i;
        if (q >= L) klim[i] = 0;
        else {
            int st = q / TPS, off = q - st * TPS;
            klim[i] = (off < NT) ? st * TPS + NT - 1 : q;
        }
    }
    int qlast = min(q0 + 63, L - 1);
    int stl = qlast / TPS, offl = qlast - stl * TPS;
    int klim_max = (offl < NT) ? stl * TPS + NT - 1 : qlast;
    int nkt = klim_max / 64 + 1;

    for (int kt = 0; kt < nkt; kt++) {
        int k0 = kt * 64;
#pragma unroll
        for (int r = 0; r < 4; r++) {
            int c = r * 256 + tid;
            int row = c >> 4;
            int d4 = (c & 15) * 4;
            int gk = k0 + row;
            float4 kv = make_float4(0, 0, 0, 0), vv = make_float4(0, 0, 0, 0);
            if (gk < L) {
                kv = *(const float4*)(kbase + (long)gk * (3 * D) + d4);
                vv = *(const float4*)(vbase + (long)gk * (3 * D) + d4);
            }
            Ks[d4 + 0][row] = kv.x; Ks[d4 + 1][row] = kv.y;
            Ks[d4 + 2][row] = kv.z; Ks[d4 + 3][row] = kv.w;
            *(float4*)&Vs[row][d4] = vv;
        }
        __syncthreads();

        float s[4][4] = {};
#pragma unroll 8
        for (int d = 0; d < 64; d++) {
            float4 a4 = *(const float4*)&Qs[d][ty * 4];
            float4 b4 = *(const float4*)&Ks[d][tx * 4];
            float ar[4] = {a4.x, a4.y, a4.z, a4.w};
            float br[4] = {b4.x, b4.y, b4.z, b4.w};
#pragma unroll
            for (int i = 0; i < 4; i++)
#pragma unroll
                for (int j = 0; j < 4; j++)
                    s[i][j] = fmaf(ar[i], br[j], s[i][j]);
        }

#pragma unroll
        for (int i = 0; i < 4; i++) {
            float rm = -1e30f;
#pragma unroll
            for (int j = 0; j < 4; j++) {
                int k = k0 + tx * 4 + j;
                s[i][j] = (k <= klim[i]) ? s[i][j] * 0.125f : -1e30f;
                rm = fmaxf(rm, s[i][j]);
            }
#pragma unroll
            for (int w = 1; w < 16; w <<= 1)
                rm = fmaxf(rm, __shfl_xor_sync(0xffffffffu, rm, w));
            float mn = fmaxf(m[i], rm);
            float corr = __expf(m[i] - mn);
            float rs = 0.0f;
#pragma unroll
            for (int j = 0; j < 4; j++) {
                float p = __expf(s[i][j] - mn);
                s[i][j] = p;
                rs += p;
            }
#pragma unroll
            for (int w = 1; w < 16; w <<= 1)
                rs += __shfl_xor_sync(0xffffffffu, rs, w);
            l[i] = l[i] * corr + rs;
            m[i] = mn;
#pragma unroll
            for (int j = 0; j < 4; j++) acc[i][j] *= corr;
        }

        __syncthreads();
#pragma unroll
        for (int j = 0; j < 4; j++) {
            float4 pv = make_float4(s[0][j], s[1][j], s[2][j], s[3][j]);
            *(float4*)&Ps[tx * 4 + j][ty * 4] = pv;
        }
        __syncthreads();

#pragma unroll 8
        for (int k = 0; k < 64; k++) {
            float4 a4 = *(const float4*)&Ps[k][ty * 4];
            float4 b4 = *(const float4*)&Vs[k][tx * 4];
            float ar[4] = {a4.x, a4.y, a4.z, a4.w};
            float br[4] = {b4.x, b4.y, b4.z, b4.w};
#pragma unroll
            for (int i = 0; i < 4; i++)
#pragma unroll
                for (int j = 0; j < 4; j++)
                    acc[i][j] = fmaf(ar[i], br[j], acc[i][j]);
        }
        __syncthreads();
    }

    // epilogue: O = acc / l, tf32-rounded, coalesced float4 store
    float* obase = g_o + (long)b * L * D + h * DH;
#pragma unroll
    for (int i = 0; i < 4; i++) {
        int q = q0 + ty * 4 + i;
        if (q >= L) continue;
        float inv = 1.0f / l[i];
        float4 o4 = make_float4(ftf32(acc[i][0] * inv), ftf32(acc[i][1] * inv),
                                ftf32(acc[i][2] * inv), ftf32(acc[i][3] * inv));
        *(float4*)(obase + (long)q * D + tx * 4) = o4;
    }
}

// -------------------- heads -------------------------------------------------
__global__ void heads_kernel(const float* __restrict__ rw, const float* __restrict__ rb,
                             const float* __restrict__ aw, const float* __restrict__ ab,
                             const float* __restrict__ ww, const float* __restrict__ wb,
                             float* __restrict__ out) {
    int bt = blockIdx.x;
    int b = bt / T, t = bt - b * T;
    __shared__ float hsh[3][D];
    int tid = threadIdx.x;
    const float* base = g_x + ((long)b * L + (long)t * TPS + (NT - 1)) * D;
    for (int d = tid; d < 3 * D; d += blockDim.x)
        hsh[d / D][d % D] = base[d];
    __syncthreads();
    if (tid < NRET) {
        float s = rb[tid];
        for (int k = 0; k < D; k++) s = fmaf(hsh[0][k], rw[(long)tid * D + k], s);
        out[(long)bt * NRET + tid] = s;
    } else if (tid < NRET + NACT) {
        int j = tid - NRET;
        float s = ab[j];
        for (int k = 0; k < D; k++) s = fmaf(hsh[1][k], aw[(long)j * D + k], s);
        out[(long)B * T * NRET + (long)bt * NACT + j] = s;
    } else if (tid < NRET + NACT + NREW) {
        int j = tid - NRET - NACT;
        float s = wb[j];
        for (int k = 0; k < D; k++) s = fmaf(hsh[2][k], ww[(long)j * D + k], s);
        out[(long)B * T * (NRET + NACT) + (long)bt * NREW + j] = s;
    }
}

// -------------------- launch ------------------------------------------------
extern "C" void kernel_launch(void* const* d_in, const int* in_sizes, int n_in,
                              void* d_out, int out_size) {
    const float* frames   = (const float*)d_in[0];
    const int*   rtg      = (const int*)d_in[1];
    const int*   actions  = (const int*)d_in[2];
    const int*   rewards  = (const int*)d_in[3];
    const int*   gids     = (const int*)d_in[4];
    const float* patch_w  = (const float*)d_in[5];
    const float* patch_b  = (const float*)d_in[6];
    const float* ret_e    = (const float*)d_in[7];
    const float* act_e    = (const float*)d_in[8];
    const float* rew_e    = (const float*)d_in[9];
    const float* game_e   = (const float*)d_in[10];
    const float* pos_e    = (const float*)d_in[11];
    const float* type_e   = (const float*)d_in[12];
    const float* qkv_w    = (const float*)d_in[13];
    const float* qkv_b    = (const float*)d_in[14];
    const float* out_w    = (const float*)d_in[15];
    const float* out_b    = (const float*)d_in[16];
    const float* ln1_s    = (const float*)d_in[17];
    const float* ln1_b    = (const float*)d_in[18];
    const float* ln2_s    = (const float*)d_in[19];
    const float* ln2_b    = (const float*)d_in[20];
    const float* ffn_w1   = (const float*)d_in[21];
    const float* ffn_b1   = (const float*)d_in[22];
    const float* ffn_w2   = (const float*)d_in[23];
    const float* ffn_b2   = (const float*)d_in[24];
    const float* ret_hw   = (const float*)d_in[25];
    const float* ret_hb   = (const float*)d_in[26];
    const float* act_hw   = (const float*)d_in[27];
    const float* act_hb   = (const float*)d_in[28];
    const float* rew_hw   = (const float*)d_in[29];
    const float* rew_hb   = (const float*)d_in[30];

    float *p_patches, *p_x, *p_xn, *p_qkv, *p_o, *p_hid, *p_wtf;
    cudaGetSymbolAddress((void**)&p_patches, g_patches);
    cudaGetSymbolAddress((void**)&p_x, g_x);
    cudaGetSymbolAddress((void**)&p_xn, g_xn);
    cudaGetSymbolAddress((void**)&p_qkv, g_qkv);
    cudaGetSymbolAddress((void**)&p_o, g_o);
    cudaGetSymbolAddress((void**)&p_hid, g_hid);
    cudaGetSymbolAddress((void**)&p_wtf, g_wtf);

    cudaFuncSetAttribute(flash_attn_kernel,
                         cudaFuncAttributeMaxDynamicSharedMemorySize, FA_SMEM_BYTES);
    cudaFuncSetAttribute(mma_gemm_kernel<0>,
                         cudaFuncAttributeMaxDynamicSharedMemorySize, MG_SMEM_BYTES);
    cudaFuncSetAttribute(mma_gemm_kernel<1>,
                         cudaFuncAttributeMaxDynamicSharedMemorySize, MG_SMEM_BYTES);
    cudaFuncSetAttribute(mma_gemm_kernel<2>,
                         cudaFuncAttributeMaxDynamicSharedMemorySize, MG_SMEM_BYTES);

    // 0. weight prep: coalesced tf32 round (no permutation)
    {
        int t0 = NL * 3 * D * D, t1 = NL * D * D, t2 = NL * DFF * D, t3 = NL * D * DFF;
        wprep_kernel<<<(t0 + 255) / 256, 256>>>(qkv_w,  p_wtf + WTF_QKV, t0);
        wprep_kernel<<<(t1 + 255) / 256, 256>>>(out_w,  p_wtf + WTF_OUT, t1);
        wprep_kernel<<<(t2 + 255) / 256, 256>>>(ffn_w1, p_wtf + WTF_F1,  t2);
        wprep_kernel<<<(t3 + 255) / 256, 256>>>(ffn_w2, p_wtf + WTF_F2,  t3);
    }

    // 1. patchify + patch embed (fp32; K=784 not divisible by 32)
    patchify_kernel<<<(NPATCH * PDIM + 255) / 256, 256>>>(frames);
    gemm_kernel<0><<<dim3(D / 64, NPATCH / 64), 256>>>(p_patches, patch_w, patch_b,
                                                       nullptr, p_o, NPATCH, D, PDIM);
    // 2. assemble sequence with embeddings -> g_x
    assemble_kernel<<<ROWS, 256>>>(rtg, actions, rewards, gids, ret_e, act_e, rew_e,
                                   game_e, pos_e, type_e);

    // 3. transformer layers
    for (int i = 0; i < NL; i++) {
        ln_kernel<<<ROWS, 256>>>(ln1_s + (long)i * D, ln1_b + (long)i * D, p_x, p_xn);
        mma_gemm_kernel<0><<<dim3(3 * D / 64, ROWS / 128), 256, MG_SMEM_BYTES>>>(
            p_xn, p_wtf + WTF_QKV + (long)i * 3 * D * D, qkv_b + (long)i * 3 * D,
            nullptr, p_qkv, ROWS, 3 * D, D);
        flash_attn_kernel<<<dim3(10, B * NH), 256, FA_SMEM_BYTES>>>();
        mma_gemm_kernel<1><<<dim3(D / 64, ROWS / 128), 256, MG_SMEM_BYTES>>>(
            p_o, p_wtf + WTF_OUT + (long)i * D * D, out_b + (long)i * D, p_x, p_x,
            ROWS, D, D);
        ln_kernel<<<ROWS, 256>>>(ln2_s + (long)i * D, ln2_b + (long)i * D, p_x, p_xn);
        mma_gemm_kernel<2><<<dim3(DFF / 64, ROWS / 128), 256, MG_SMEM_BYTES>>>(
            p_xn, p_wtf + WTF_F1 + (long)i * DFF * D, ffn_b1 + (long)i * DFF,
            nullptr, p_hid, ROWS, DFF, D);
        mma_gemm_kernel<1><<<dim3(D / 64, ROWS / 128), 256, MG_SMEM_BYTES>>>(
            p_hid, p_wtf + WTF_F2 + (long)i * D * DFF, ffn_b2 + (long)i * D, p_x, p_x,
            ROWS, D, DFF);
    }

    // 4. heads
    heads_kernel<<<B * T, 256>>>(ret_hw, ret_hb, act_hw, act_hb, rew_hw, rew_hb,
                                 (float*)d_out);
}

// round 14
// speedup vs baseline: 1.1204x; 1.0263x over previous
#include <cuda_runtime.h>
#include <math.h>
#include <stdint.h>

// ---------------------------------------------------------------------------
// MGDT forward. tf32 tensor-core linears (mma.sync m16n8k8), operands
// pre-rounded to tf32 in gmem (float4 weight-prep + producer-side rounding),
// cp.async double-buffered mainloop (zero cvts). Fused fp32 flash attention
// (prefix mask). Shuffle-based LayerNorm. fp32 patch embed.
// Shapes: B=8 T=16 C=4 H=W=84 P=14 NT=36 TPS=39 L=624 D=512 NH=8 DH=64 NL=6
//         DFF=2048 NRET=120 NACT=18 NREW=3
// ---------------------------------------------------------------------------

namespace cfg {
constexpr int B = 8, T = 16, C = 4, H = 84, W = 84, P = 14;
constexpr int NT = 36, TPS = 39, L = 624;
constexpr int D = 512, NH = 8, DH = 64, NL = 6, DFF = 2048;
constexpr int NRET = 120, NACT = 18, NREW = 3;
constexpr int ROWS = B * L;            // 4992
constexpr int NPATCH = B * T * NT;     // 4608
constexpr int PDIM = C * P * P;        // 784
}

using namespace cfg;

// tf32-rounded weight scratch offsets (contiguous layout, no permutation)
constexpr long WTF_QKV = 0;
constexpr long WTF_OUT = (long)NL * 3 * D * D;
constexpr long WTF_F1  = WTF_OUT + (long)NL * D * D;
constexpr long WTF_F2  = WTF_F1 + (long)NL * DFF * D;
constexpr long WTF_TOTAL = WTF_F2 + (long)NL * D * DFF;

// -------------------- scratch (device globals; no runtime alloc) -----------
__device__ float g_patches[NPATCH * PDIM];
__device__ float g_x[ROWS * D];        // residual stream (raw fp32)
__device__ float g_xn[ROWS * D];       // tf32-rounded (GEMM-A only)
__device__ float g_qkv[ROWS * 3 * D];  // raw fp32 (flash input)
__device__ float g_o[ROWS * D];        // patch path raw; attn out tf32-rounded
__device__ float g_hid[ROWS * DFF];    // tf32-rounded (GEMM-A only)
__device__ float g_wtf[WTF_TOTAL];     // tf32-rounded weights

__device__ __forceinline__ float ftf32(float x) {
    uint32_t u;
    asm("cvt.rna.tf32.f32 %0, %1;" : "=r"(u) : "f"(x));
    return __uint_as_float(u);
}

// -------------------- weight prep: float4 coalesced tf32 round --------------
__global__ void wprep_kernel(const float4* __restrict__ src, float4* __restrict__ dst,
                             int total4) {
    int i = blockIdx.x * blockDim.x + threadIdx.x;
    if (i >= total4) return;
    float4 v = src[i];
    dst[i] = make_float4(ftf32(v.x), ftf32(v.y), ftf32(v.z), ftf32(v.w));
}

// -------------------- patch extraction -------------------------------------
__global__ void patchify_kernel(const float* __restrict__ frames) {
    int i = blockIdx.x * blockDim.x + threadIdx.x;
    if (i >= NPATCH * PDIM) return;
    int prow = i / PDIM, f = i - prow * PDIM;
    int bt = prow / NT, n = prow - bt * NT;
    int gy = n / 6, gx = n - gy * 6;
    int c = f / (P * P);
    int r = f - c * P * P;
    int py = r / P, px = r - py * P;
    long src = (((long)bt * C + c) * H + gy * P + py) * W + gx * P + px;
    g_patches[i] = frames[src];
}

// -------------------- fp32 GEMM (patch embed only) --------------------------
template <int EPI>
__global__ void gemm_kernel(const float* __restrict__ A, const float* __restrict__ Wm,
                            const float* __restrict__ bias, const float* __restrict__ res,
                            float* __restrict__ Cmat, int M, int N, int K) {
    __shared__ float As[16][68];
    __shared__ float Bs[16][68];
    int tid = threadIdx.x;
    int bm = blockIdx.y * 64, bn = blockIdx.x * 64;
    int lr = tid >> 2;
    int lk = (tid & 3) * 4;
    int ty = tid >> 4, tx = tid & 15;
    float acc[4][4] = {};
    const float* Aptr = A + (long)(bm + lr) * K + lk;
    const float* Wptr = Wm + (long)(bn + lr) * K + lk;
    for (int k0 = 0; k0 < K; k0 += 16) {
        float4 av = *(const float4*)(Aptr + k0);
        float4 wv = *(const float4*)(Wptr + k0);
        As[lk + 0][lr] = av.x; As[lk + 1][lr] = av.y;
        As[lk + 2][lr] = av.z; As[lk + 3][lr] = av.w;
        Bs[lk + 0][lr] = wv.x; Bs[lk + 1][lr] = wv.y;
        Bs[lk + 2][lr] = wv.z; Bs[lk + 3][lr] = wv.w;
        __syncthreads();
#pragma unroll
        for (int kk = 0; kk < 16; kk++) {
            float4 a4 = *(const float4*)&As[kk][ty * 4];
            float4 b4 = *(const float4*)&Bs[kk][tx * 4];
            float ar[4] = {a4.x, a4.y, a4.z, a4.w};
            float br[4] = {b4.x, b4.y, b4.z, b4.w};
#pragma unroll
            for (int i = 0; i < 4; i++)
#pragma unroll
                for (int j = 0; j < 4; j++)
                    acc[i][j] = fmaf(ar[i], br[j], acc[i][j]);
        }
        __syncthreads();
    }
#pragma unroll
    for (int i = 0; i < 4; i++) {
        int row = bm + ty * 4 + i;
#pragma unroll
        for (int j = 0; j < 4; j++) {
            int col = bn + tx * 4 + j;
            float v = acc[i][j] + bias[col];
            if (EPI == 1) v += res[(long)row * N + col];
            if (EPI == 2) v = 0.5f * v * (1.0f + erff(v * 0.70710678118654752f));
            Cmat[(long)row * N + col] = v;
        }
    }
}

// -------------------- tf32 MMA GEMM, cp.async, pre-rounded operands ---------
// C = A(MxK) @ W(NxK)^T + bias. A and W are already tf32-rounded in gmem ->
// mainloop has no cvts. Block 128x64, 8 warps (4M x 2N), warp tile 32x32,
// k-tile 32, 2-stage cp.async pipeline, scalar-LDS fragments.
// EPI: 0 none (raw store), 1 residual add (raw store), 2 GELU (tf32 store,
// since g_hid feeds ffn2 as A).
constexpr int MG_STAGE_FLOATS = 128 * 36 + 64 * 36;      // 6912
constexpr int MG_SMEM_BYTES = 2 * MG_STAGE_FLOATS * 4;   // 55296

template <int EPI>
__global__ __launch_bounds__(256) void mma_gemm_kernel(
        const float* __restrict__ A, const float* __restrict__ Wm,
        const float* __restrict__ bias, const float* __restrict__ res,
        float* __restrict__ Cmat, int M, int N, int K) {
    extern __shared__ float mg_smem[];
    int tid = threadIdx.x;
    int bm = blockIdx.y * 128, bn = blockIdx.x * 64;
    int warp = tid >> 5, lane = tid & 31;
    int grp = lane >> 2, qd = lane & 3;
    int wm0 = (warp >> 1) * 32, wn0 = (warp & 1) * 32;
    float acc[2][4][4] = {};

    int arow = tid >> 3;             // 0..31
    int af4 = (tid & 7) * 4;         // 0,4,..,28

    auto prefetch = [&](int k0, int s) {
        float* As = mg_smem + s * MG_STAGE_FLOATS;
        float* Bs = As + 128 * 36;
#pragma unroll
        for (int i = 0; i < 4; i++) {
            int r = arow + 32 * i;
            uint32_t dst = (uint32_t)__cvta_generic_to_shared(&As[r * 36 + af4]);
            const float* src = A + (long)(bm + r) * K + k0 + af4;
            asm volatile("cp.async.cg.shared.global [%0], [%1], 16;\n"
                         :: "r"(dst), "l"(src));
        }
#pragma unroll
        for (int i = 0; i < 2; i++) {
            int idx = tid + 256 * i;
            int r = idx >> 3;
            int f4 = (idx & 7) * 4;
            uint32_t dst = (uint32_t)__cvta_generic_to_shared(&Bs[r * 36 + f4]);
            const float* src = Wm + (long)(bn + r) * K + k0 + f4;
            asm volatile("cp.async.cg.shared.global [%0], [%1], 16;\n"
                         :: "r"(dst), "l"(src));
        }
        asm volatile("cp.async.commit_group;\n");
    };

    int KT = K / 32;
    prefetch(0, 0);
    for (int kt = 0; kt < KT; kt++) {
        if (kt + 1 < KT) {
            prefetch((kt + 1) * 32, (kt + 1) & 1);
            asm volatile("cp.async.wait_group 1;\n");
        } else {
            asm volatile("cp.async.wait_group 0;\n");
        }
        __syncthreads();
        const float* As = mg_smem + (kt & 1) * MG_STAGE_FLOATS;
        const float* Bs = As + 128 * 36;
#pragma unroll
        for (int ks = 0; ks < 4; ks++) {
            uint32_t a[2][4];
            uint32_t b[4][2];
#pragma unroll
            for (int mi = 0; mi < 2; mi++) {
                int r = wm0 + mi * 16 + grp;
                int kk = ks * 8 + qd;
                a[mi][0] = __float_as_uint(As[r * 36 + kk]);
                a[mi][1] = __float_as_uint(As[(r + 8) * 36 + kk]);
                a[mi][2] = __float_as_uint(As[r * 36 + kk + 4]);
                a[mi][3] = __float_as_uint(As[(r + 8) * 36 + kk + 4]);
            }
#pragma unroll
            for (int ni = 0; ni < 4; ni++) {
                int c = wn0 + ni * 8 + grp;
                int kk = ks * 8 + qd;
                b[ni][0] = __float_as_uint(Bs[c * 36 + kk]);
                b[ni][1] = __float_as_uint(Bs[c * 36 + kk + 4]);
            }
#pragma unroll
            for (int mi = 0; mi < 2; mi++)
#pragma unroll
                for (int ni = 0; ni < 4; ni++)
                    asm volatile(
                        "mma.sync.aligned.m16n8k8.row.col.f32.tf32.tf32.f32 "
                        "{%0,%1,%2,%3},{%4,%5,%6,%7},{%8,%9},{%0,%1,%2,%3};\n"
                        : "+f"(acc[mi][ni][0]), "+f"(acc[mi][ni][1]),
                          "+f"(acc[mi][ni][2]), "+f"(acc[mi][ni][3])
                        : "r"(a[mi][0]), "r"(a[mi][1]), "r"(a[mi][2]), "r"(a[mi][3]),
                          "r"(b[ni][0]), "r"(b[ni][1]));
        }
        __syncthreads();
    }
#pragma unroll
    for (int mi = 0; mi < 2; mi++) {
#pragma unroll
        for (int ni = 0; ni < 4; ni++) {
            int r = bm + wm0 + mi * 16 + grp;
            int c = bn + wn0 + ni * 8 + 2 * qd;
            float b0 = bias[c], b1 = bias[c + 1];
#pragma unroll
            for (int h = 0; h < 2; h++) {
                int row = r + 8 * h;
                float v0 = acc[mi][ni][2 * h + 0] + b0;
                float v1 = acc[mi][ni][2 * h + 1] + b1;
                if (EPI == 1) {
                    const float2 rr = *(const float2*)(res + (long)row * N + c);
                    v0 += rr.x; v1 += rr.y;
                }
                if (EPI == 2) {
                    v0 = 0.5f * v0 * (1.0f + erff(v0 * 0.70710678118654752f));
                    v1 = 0.5f * v1 * (1.0f + erff(v1 * 0.70710678118654752f));
                    v0 = ftf32(v0);   // g_hid is GEMM-A of ffn2
                    v1 = ftf32(v1);
                }
                *(float2*)(Cmat + (long)row * N + c) = make_float2(v0, v1);
            }
        }
    }
}

// -------------------- layernorm (shuffle reductions, 2 syncs) ---------------
// 256 threads/row; warp butterfly -> 8 partials -> broadcast. Writes
// tf32-rounded output (consumed only as GEMM-A).
__global__ void ln_kernel(const float* __restrict__ s, const float* __restrict__ bta,
                          const float* __restrict__ in, float* __restrict__ out) {
    int row = blockIdx.x;
    const float* x = in + (long)row * D;
    int tid = threadIdx.x;
    int wid = tid >> 5, lane = tid & 31;
    float v0 = x[tid], v1 = x[tid + 256];
    __shared__ float p1[8], p2[8];

    float sum = v0 + v1;
#pragma unroll
    for (int w = 16; w > 0; w >>= 1)
        sum += __shfl_xor_sync(0xffffffffu, sum, w);
    if (lane == 0) p1[wid] = sum;
    __syncthreads();
    float tot = p1[0] + p1[1] + p1[2] + p1[3] + p1[4] + p1[5] + p1[6] + p1[7];
    float mu = tot * (1.0f / 512.0f);

    float d0 = v0 - mu, d1 = v1 - mu;
    float vs = d0 * d0 + d1 * d1;
#pragma unroll
    for (int w = 16; w > 0; w >>= 1)
        vs += __shfl_xor_sync(0xffffffffu, vs, w);
    if (lane == 0) p2[wid] = vs;
    __syncthreads();
    float vtot = p2[0] + p2[1] + p2[2] + p2[3] + p2[4] + p2[5] + p2[6] + p2[7];
    float rstd = rsqrtf(vtot * (1.0f / 512.0f) + 1e-5f);

    float* o = out + (long)row * D;
    o[tid]       = ftf32(d0 * rstd * s[tid]       + bta[tid]);
    o[tid + 256] = ftf32(d1 * rstd * s[tid + 256] + bta[tid + 256]);
}

// -------------------- token assembly ----------------------------------------
__global__ void assemble_kernel(const int* __restrict__ rtg, const int* __restrict__ act,
                                const int* __restrict__ rew, const int* __restrict__ gid,
                                const float* __restrict__ ret_e, const float* __restrict__ act_e,
                                const float* __restrict__ rew_e, const float* __restrict__ game_e,
                                const float* __restrict__ pos_e, const float* __restrict__ type_e) {
    int row = blockIdx.x;
    int b = row / L, l = row - b * L;
    int t = l / TPS, off = l - t * TPS;
    int tid = threadIdx.x;
    const float* src;
    int typ;
    if (off < NT)           { src = g_o + ((long)(b * T + t) * NT + off) * D; typ = 0; }
    else if (off == NT)     { src = ret_e + (long)rtg[b * T + t] * D;        typ = 1; }
    else if (off == NT + 1) { src = act_e + (long)act[b * T + t] * D;        typ = 2; }
    else                    { src = rew_e + (long)rew[b * T + t] * D;        typ = 3; }
    int g = gid[b];
    float* dst = g_x + (long)row * D;
    for (int d = tid; d < D; d += blockDim.x)
        dst[d] = src[d] + pos_e[(long)l * D + d] + type_e[(long)typ * D + d]
               + game_e[(long)g * D + d];
}

// -------------------- fused flash attention (fp32, dynamic smem) ------------
// Mask is a per-row PREFIX: allowed(q,k) <=> k <= klim(q); klim monotone in q.
// Epilogue writes g_o tf32-rounded (consumed only by out-proj GEMM as A).
constexpr int FA_TILE_FLOATS = 64 * 68;
constexpr int FA_SMEM_BYTES = 4 * FA_TILE_FLOATS * 4;

__global__ __launch_bounds__(256) void flash_attn_kernel() {
    extern __shared__ float fa_smem[];
    float (*Qs)[68] = (float(*)[68])(fa_smem);                      // [d][q]
    float (*Ks)[68] = (float(*)[68])(fa_smem + FA_TILE_FLOATS);     // [d][k]
    float (*Vs)[68] = (float(*)[68])(fa_smem + 2 * FA_TILE_FLOATS); // [k][d]
    float (*Ps)[68] = (float(*)[68])(fa_smem + 3 * FA_TILE_FLOATS); // [k][q]
    int bh = blockIdx.y;
    int b = bh >> 3, h = bh & 7;
    int q0 = blockIdx.x * 64;
    int tid = threadIdx.x;
    int ty = tid >> 4, tx = tid & 15;
    const float* qbase = g_qkv + (long)b * L * (3 * D) + h * DH;
    const float* kbase = qbase + D;
    const float* vbase = qbase + 2 * D;

#pragma unroll
    for (int r = 0; r < 4; r++) {
        int c = r * 256 + tid;
        int row = c >> 4;
        int d4 = (c & 15) * 4;
        float4 qv = make_float4(0, 0, 0, 0);
        int gq = q0 + row;
        if (gq < L) qv = *(const float4*)(qbase + (long)gq * (3 * D) + d4);
        Qs[d4 + 0][row] = qv.x; Qs[d4 + 1][row] = qv.y;
        Qs[d4 + 2][row] = qv.z; Qs[d4 + 3][row] = qv.w;
    }

    float m[4], l[4], acc[4][4];
#pragma unroll
    for (int i = 0; i < 4; i++) {
        m[i] = -1e30f; l[i] = 0.0f;
#pragma unroll
        for (int j = 0; j < 4; j++) acc[i][j] = 0.0f;
    }

    int klim[4];
#pragma unroll
    for (int i = 0; i < 4; i++) {
        int q = q0 + ty * 4 + i;
        if (q >= L) klim[i] = 0;
        else {
            int st = q / TPS, off = q - st * TPS;
            klim[i] = (off < NT) ? st * TPS + NT - 1 : q;
        }
    }
    int qlast = min(q0 + 63, L - 1);
    int stl = qlast / TPS, offl = qlast - stl * TPS;
    int klim_max = (offl < NT) ? stl * TPS + NT - 1 : qlast;
    int nkt = klim_max / 64 + 1;

    for (int kt = 0; kt < nkt; kt++) {
        int k0 = kt * 64;
#pragma unroll
        for (int r = 0; r < 4; r++) {
            int c = r * 256 + tid;
            int row = c >> 4;
            int d4 = (c & 15) * 4;
            int gk = k0 + row;
            float4 kv = make_float4(0, 0, 0, 0), vv = make_float4(0, 0, 0, 0);
            if (gk < L) {
                kv = *(const float4*)(kbase + (long)gk * (3 * D) + d4);
                vv = *(const float4*)(vbase + (long)gk * (3 * D) + d4);
            }
            Ks[d4 + 0][row] = kv.x; Ks[d4 + 1][row] = kv.y;
            Ks[d4 + 2][row] = kv.z; Ks[d4 + 3][row] = kv.w;
            *(float4*)&Vs[row][d4] = vv;
        }
        __syncthreads();

        float s[4][4] = {};
#pragma unroll 8
        for (int d = 0; d < 64; d++) {
            float4 a4 = *(const float4*)&Qs[d][ty * 4];
            float4 b4 = *(const float4*)&Ks[d][tx * 4];
            float ar[4] = {a4.x, a4.y, a4.z, a4.w};
            float br[4] = {b4.x, b4.y, b4.z, b4.w};
#pragma unroll
            for (int i = 0; i < 4; i++)
#pragma unroll
                for (int j = 0; j < 4; j++)
                    s[i][j] = fmaf(ar[i], br[j], s[i][j]);
        }

#pragma unroll
        for (int i = 0; i < 4; i++) {
            float rm = -1e30f;
#pragma unroll
            for (int j = 0; j < 4; j++) {
                int k = k0 + tx * 4 + j;
                s[i][j] = (k <= klim[i]) ? s[i][j] * 0.125f : -1e30f;
                rm = fmaxf(rm, s[i][j]);
            }
#pragma unroll
            for (int w = 1; w < 16; w <<= 1)
                rm = fmaxf(rm, __shfl_xor_sync(0xffffffffu, rm, w));
            float mn = fmaxf(m[i], rm);
            float corr = __expf(m[i] - mn);
            float rs = 0.0f;
#pragma unroll
            for (int j = 0; j < 4; j++) {
                float p = __expf(s[i][j] - mn);
                s[i][j] = p;
                rs += p;
            }
#pragma unroll
            for (int w = 1; w < 16; w <<= 1)
                rs += __shfl_xor_sync(0xffffffffu, rs, w);
            l[i] = l[i] * corr + rs;
            m[i] = mn;
#pragma unroll
            for (int j = 0; j < 4; j++) acc[i][j] *= corr;
        }

        __syncthreads();
#pragma unroll
        for (int j = 0; j < 4; j++) {
            float4 pv = make_float4(s[0][j], s[1][j], s[2][j], s[3][j]);
            *(float4*)&Ps[tx * 4 + j][ty * 4] = pv;
        }
        __syncthreads();

#pragma unroll 8
        for (int k = 0; k < 64; k++) {
            float4 a4 = *(const float4*)&Ps[k][ty * 4];
            float4 b4 = *(const float4*)&Vs[k][tx * 4];
            float ar[4] = {a4.x, a4.y, a4.z, a4.w};
            float br[4] = {b4.x, b4.y, b4.z, b4.w};
#pragma unroll
            for (int i = 0; i < 4; i++)
#pragma unroll
                for (int j = 0; j < 4; j++)
                    acc[i][j] = fmaf(ar[i], br[j], acc[i][j]);
        }
        __syncthreads();
    }

    // epilogue: O = acc / l, tf32-rounded, coalesced float4 store
    float* obase = g_o + (long)b * L * D + h * DH;
#pragma unroll
    for (int i = 0; i < 4; i++) {
        int q = q0 + ty * 4 + i;
        if (q >= L) continue;
        float inv = 1.0f / l[i];
        float4 o4 = make_float4(ftf32(acc[i][0] * inv), ftf32(acc[i][1] * inv),
                                ftf32(acc[i][2] * inv), ftf32(acc[i][3] * inv));
        *(float4*)(obase + (long)q * D + tx * 4) = o4;
    }
}

// -------------------- heads -------------------------------------------------
__global__ void heads_kernel(const float* __restrict__ rw, const float* __restrict__ rb,
                             const float* __restrict__ aw, const float* __restrict__ ab,
                             const float* __restrict__ ww, const float* __restrict__ wb,
                             float* __restrict__ out) {
    int bt = blockIdx.x;
    int b = bt / T, t = bt - b * T;
    __shared__ float hsh[3][D];
    int tid = threadIdx.x;
    const float* base = g_x + ((long)b * L + (long)t * TPS + (NT - 1)) * D;
    for (int d = tid; d < 3 * D; d += blockDim.x)
        hsh[d / D][d % D] = base[d];
    __syncthreads();
    if (tid < NRET) {
        float s = rb[tid];
        for (int k = 0; k < D; k++) s = fmaf(hsh[0][k], rw[(long)tid * D + k], s);
        out[(long)bt * NRET + tid] = s;
    } else if (tid < NRET + NACT) {
        int j = tid - NRET;
        float s = ab[j];
        for (int k = 0; k < D; k++) s = fmaf(hsh[1][k], aw[(long)j * D + k], s);
        out[(long)B * T * NRET + (long)bt * NACT + j] = s;
    } else if (tid < NRET + NACT + NREW) {
        int j = tid - NRET - NACT;
        float s = wb[j];
        for (int k = 0; k < D; k++) s = fmaf(hsh[2][k], ww[(long)j * D + k], s);
        out[(long)B * T * (NRET + NACT) + (long)bt * NREW + j] = s;
    }
}

// -------------------- launch ------------------------------------------------
extern "C" void kernel_launch(void* const* d_in, const int* in_sizes, int n_in,
                              void* d_out, int out_size) {
    const float* frames   = (const float*)d_in[0];
    const int*   rtg      = (const int*)d_in[1];
    const int*   actions  = (const int*)d_in[2];
    const int*   rewards  = (const int*)d_in[3];
    const int*   gids     = (const int*)d_in[4];
    const float* patch_w  = (const float*)d_in[5];
    const float* patch_b  = (const float*)d_in[6];
    const float* ret_e    = (const float*)d_in[7];
    const float* act_e    = (const float*)d_in[8];
    const float* rew_e    = (const float*)d_in[9];
    const float* game_e   = (const float*)d_in[10];
    const float* pos_e    = (const float*)d_in[11];
    const float* type_e   = (const float*)d_in[12];
    const float* qkv_w    = (const float*)d_in[13];
    const float* qkv_b    = (const float*)d_in[14];
    const float* out_w    = (const float*)d_in[15];
    const float* out_b    = (const float*)d_in[16];
    const float* ln1_s    = (const float*)d_in[17];
    const float* ln1_b    = (const float*)d_in[18];
    const float* ln2_s    = (const float*)d_in[19];
    const float* ln2_b    = (const float*)d_in[20];
    const float* ffn_w1   = (const float*)d_in[21];
    const float* ffn_b1   = (const float*)d_in[22];
    const float* ffn_w2   = (const float*)d_in[23];
    const float* ffn_b2   = (const float*)d_in[24];
    const float* ret_hw   = (const float*)d_in[25];
    const float* ret_hb   = (const float*)d_in[26];
    const float* act_hw   = (const float*)d_in[27];
    const float* act_hb   = (const float*)d_in[28];
    const float* rew_hw   = (const float*)d_in[29];
    const float* rew_hb   = (const float*)d_in[30];

    float *p_patches, *p_x, *p_xn, *p_qkv, *p_o, *p_hid, *p_wtf;
    cudaGetSymbolAddress((void**)&p_patches, g_patches);
    cudaGetSymbolAddress((void**)&p_x, g_x);
    cudaGetSymbolAddress((void**)&p_xn, g_xn);
    cudaGetSymbolAddress((void**)&p_qkv, g_qkv);
    cudaGetSymbolAddress((void**)&p_o, g_o);
    cudaGetSymbolAddress((void**)&p_hid, g_hid);
    cudaGetSymbolAddress((void**)&p_wtf, g_wtf);

    cudaFuncSetAttribute(flash_attn_kernel,
                         cudaFuncAttributeMaxDynamicSharedMemorySize, FA_SMEM_BYTES);
    cudaFuncSetAttribute(mma_gemm_kernel<0>,
                         cudaFuncAttributeMaxDynamicSharedMemorySize, MG_SMEM_BYTES);
    cudaFuncSetAttribute(mma_gemm_kernel<1>,
                         cudaFuncAttributeMaxDynamicSharedMemorySize, MG_SMEM_BYTES);
    cudaFuncSetAttribute(mma_gemm_kernel<2>,
                         cudaFuncAttributeMaxDynamicSharedMemorySize, MG_SMEM_BYTES);

    // 0. weight prep: float4 coalesced tf32 round (no permutation)
    {
        int t0 = NL * 3 * D * D / 4, t1 = NL * D * D / 4;
        int t2 = NL * DFF * D / 4,   t3 = NL * D * DFF / 4;
        wprep_kernel<<<(t0 + 255) / 256, 256>>>((const float4*)qkv_w,
                                                (float4*)(p_wtf + WTF_QKV), t0);
        wprep_kernel<<<(t1 + 255) / 256, 256>>>((const float4*)out_w,
                                                (float4*)(p_wtf + WTF_OUT), t1);
        wprep_kernel<<<(t2 + 255) / 256, 256>>>((const float4*)ffn_w1,
                                                (float4*)(p_wtf + WTF_F1), t2);
        wprep_kernel<<<(t3 + 255) / 256, 256>>>((const float4*)ffn_w2,
                                                (float4*)(p_wtf + WTF_F2), t3);
    }

    // 1. patchify + patch embed (fp32; K=784 not divisible by 32)
    patchify_kernel<<<(NPATCH * PDIM + 255) / 256, 256>>>(frames);
    gemm_kernel<0><<<dim3(D / 64, NPATCH / 64), 256>>>(p_patches, patch_w, patch_b,
                                                       nullptr, p_o, NPATCH, D, PDIM);
    // 2. assemble sequence with embeddings -> g_x
    assemble_kernel<<<ROWS, 256>>>(rtg, actions, rewards, gids, ret_e, act_e, rew_e,
                                   game_e, pos_e, type_e);

    // 3. transformer layers
    for (int i = 0; i < NL; i++) {
        ln_kernel<<<ROWS, 256>>>(ln1_s + (long)i * D, ln1_b + (long)i * D, p_x, p_xn);
        mma_gemm_kernel<0><<<dim3(3 * D / 64, ROWS / 128), 256, MG_SMEM_BYTES>>>(
            p_xn, p_wtf + WTF_QKV + (long)i * 3 * D * D, qkv_b + (long)i * 3 * D,
            nullptr, p_qkv, ROWS, 3 * D, D);
        flash_attn_kernel<<<dim3(10, B * NH), 256, FA_SMEM_BYTES>>>();
        mma_gemm_kernel<1><<<dim3(D / 64, ROWS / 128), 256, MG_SMEM_BYTES>>>(
            p_o, p_wtf + WTF_OUT + (long)i * D * D, out_b + (long)i * D, p_x, p_x,
            ROWS, D, D);
        ln_kernel<<<ROWS, 256>>>(ln2_s + (long)i * D, ln2_b + (long)i * D, p_x, p_xn);
        mma_gemm_kernel<2><<<dim3(DFF / 64, ROWS / 128), 256, MG_SMEM_BYTES>>>(
            p_xn, p_wtf + WTF_F1 + (long)i * DFF * D, ffn_b1 + (long)i * DFF,
            nullptr, p_hid, ROWS, DFF, D);
        mma_gemm_kernel<1><<<dim3(D / 64, ROWS / 128), 256, MG_SMEM_BYTES>>>(
            p_hid, p_wtf + WTF_F2 + (long)i * D * DFF, ffn_b2 + (long)i * D, p_x, p_x,
            ROWS, D, DFF);
    }

    // 4. heads
    heads_kernel<<<B * T, 256>>>(ret_hw, ret_hb, act_hw, act_hb, rew_hw, rew_hb,
                                 (float*)d_out);
}